// round 12
// baseline (speedup 1.0000x reference)
#include <cuda_runtime.h>
#include <cuda_fp16.h>
#include <math.h>
#include <cstdint>

typedef __half h16;

// Problem constants
#define NBATCH 2
#define SEQ    2048
#define NHEAD  16
#define DHEAD  128
#define HID    2048
#define NTOK   4096   // NBATCH*SEQ

// Scratch (device globals — no runtime allocation allowed)
__device__ h16 g_Qf[NBATCH*NHEAD*SEQ*DHEAD];    // post-RoPE, single fp16
__device__ h16 g_Kf[NBATCH*NHEAD*SEQ*DHEAD];
__device__ h16 g_Vh[NBATCH*NHEAD*SEQ*DHEAD];    // V hi/lo fp16 (direct path)
__device__ h16 g_Vl[NBATCH*NHEAD*SEQ*DHEAD];

__device__ h16 g_xh[(size_t)NTOK*HID];          // x single fp16
__device__ h16 g_ch[(size_t)NTOK*HID];          // ctx single fp16 (flash output)
__device__ h16 g_wh[4][(size_t)HID*HID];        // weights hi/lo
__device__ h16 g_wl[4][(size_t)HID*HID];

__device__ float2 g_cs[SEQ*DHEAD];              // (cos, sin) of freqs

// ---------------------------------------------------------------------------
// helpers
// ---------------------------------------------------------------------------
__device__ __forceinline__ uint32_t smem_u32(const void* p) {
    uint32_t a;
    asm("{ .reg .u64 t; cvta.to.shared.u64 t, %1; cvt.u32.u64 %0, t; }"
        : "=r"(a) : "l"(p));
    return a;
}
__device__ __forceinline__ void ldm4(uint32_t* r, uint32_t addr) {
    asm volatile("ldmatrix.sync.aligned.m8n8.x4.shared.b16 {%0,%1,%2,%3},[%4];"
                 : "=r"(r[0]), "=r"(r[1]), "=r"(r[2]), "=r"(r[3]) : "r"(addr));
}
__device__ __forceinline__ void ldm4t(uint32_t* r, uint32_t addr) {
    asm volatile("ldmatrix.sync.aligned.m8n8.x4.trans.shared.b16 {%0,%1,%2,%3},[%4];"
                 : "=r"(r[0]), "=r"(r[1]), "=r"(r[2]), "=r"(r[3]) : "r"(addr));
}
__device__ __forceinline__ void mma16816(float* d, const uint32_t* a,
                                         uint32_t b0, uint32_t b1) {
    asm volatile(
        "mma.sync.aligned.m16n8k16.row.col.f32.f16.f16.f32 "
        "{%0,%1,%2,%3},{%4,%5,%6,%7},{%8,%9},{%0,%1,%2,%3};"
        : "+f"(d[0]), "+f"(d[1]), "+f"(d[2]), "+f"(d[3])
        : "r"(a[0]), "r"(a[1]), "r"(a[2]), "r"(a[3]), "r"(b0), "r"(b1));
}
__device__ __forceinline__ uint32_t packh2(h16 a, h16 b) {
    return ((uint32_t)__half_as_ushort(b) << 16) | __half_as_ushort(a);
}
__device__ __forceinline__ void split1h(float v, h16& h, h16& l) {
    h = __float2half_rn(v);
    l = __float2half_rn(v - __half2float(h));
}
__device__ __forceinline__ void split2packh(float a, float b,
                                            uint32_t& hp, uint32_t& lp) {
    h16 ha, la, hb, lb;
    split1h(a, ha, la);
    split1h(b, hb, lb);
    hp = packh2(ha, hb);
    lp = packh2(la, lb);
}
__device__ __forceinline__ void cpa16(uint32_t s, const void* g) {
    asm volatile("cp.async.cg.shared.global [%0], [%1], 16;" :: "r"(s), "l"(g));
}
#define CP_COMMIT() asm volatile("cp.async.commit_group;" ::: "memory")
#define CP_WAIT0()  asm volatile("cp.async.wait_group 0;" ::: "memory")
#define CP_WAIT1()  asm volatile("cp.async.wait_group 1;" ::: "memory")

// ---------------------------------------------------------------------------
// cos/sin table from freqs
// ---------------------------------------------------------------------------
__global__ __launch_bounds__(256)
void build_cs(const float* __restrict__ freqs)
{
    int i = blockIdx.x * 256 + threadIdx.x;
    float f = freqs[i];
    g_cs[i] = make_float2(cosf(f), sinf(f));
}

// ---------------------------------------------------------------------------
// Fused split: x -> single fp16; 4 weights -> fp16 hi + lo. One launch.
// ---------------------------------------------------------------------------
__global__ __launch_bounds__(256)
void split_all(const float* __restrict__ x,
               const float* __restrict__ w0, const float* __restrict__ w1,
               const float* __restrict__ w2, const float* __restrict__ w3,
               h16* __restrict__ xh,
               h16* __restrict__ whb, h16* __restrict__ wlb)
{
    const int XQ = NTOK * HID / 4;
    const int WQ = HID * HID / 4;
    int i = blockIdx.x * 256 + threadIdx.x;
    if (i < XQ) {
        float4 v = ((const float4*)x)[i];
        ((uint2*)xh)[i] = make_uint2(
            packh2(__float2half_rn(v.x), __float2half_rn(v.y)),
            packh2(__float2half_rn(v.z), __float2half_rn(v.w)));
        return;
    }
    int j = i - XQ;
    int widx = j >> 20;
    int off = j & (WQ - 1);
    const float* src = (widx == 0) ? w0 : (widx == 1) ? w1 : (widx == 2) ? w2 : w3;
    h16* dh = whb + (size_t)widx * HID * HID;
    h16* dl = wlb + (size_t)widx * HID * HID;
    float4 v = ((const float4*)src)[off];
    float vv[4] = {v.x, v.y, v.z, v.w};
    h16 hh[4], ll[4];
    #pragma unroll
    for (int q = 0; q < 4; q++) split1h(vv[q], hh[q], ll[q]);
    ((uint2*)dh)[off] = make_uint2(packh2(hh[0], hh[1]), packh2(hh[2], hh[3]));
    ((uint2*)dl)[off] = make_uint2(packh2(ll[0], ll[1]), packh2(ll[2], ll[3]));
}

// ---------------------------------------------------------------------------
// GEMM core: 128x128 tile, cp.async 3-stage pipeline, NPROD in {1,2}.
// NPROD=1: D = A·Bh          (A single, B hi)
// NPROD=2: D = A·Bh + A·Bl   (A single, B hi/lo — weight-exact)
// ropePerm permutes B smem rows so accumulators pair (d, d+64).
// ---------------------------------------------------------------------------
#define SPAD 40
#define ARR_B   (128*SPAD*2)          // 10240
#define GEMM_SMEM (3 * 3 * ARR_B)     // 92160 (3 stages; NPROD=1 uses 2 arrays)

template<int NPROD>
__device__ __forceinline__ void gemm_core(
    const h16* __restrict__ pA,
    const h16* __restrict__ pBh, const h16* __restrict__ pBl,
    uint32_t ub, bool ropePerm, float acc[4][4][4])
{
    constexpr int STB = (NPROD == 2 ? 3 : 2) * ARR_B;
    const int t    = threadIdx.x;
    const int wid  = t >> 5;
    const int lane = t & 31;
    const int wm   = wid & 1;
    const int wn   = wid >> 1;
    const int lrow = lane & 15, lcol = lane >> 4;

    int rowL[2], qdL[2];
    #pragma unroll
    for (int r = 0; r < 2; r++) {
        int u = t + (r << 8);
        rowL[r] = u >> 2;
        qdL[r]  = u & 3;
    }

    #pragma unroll
    for (int i = 0; i < 4; i++)
        #pragma unroll
        for (int j = 0; j < 4; j++)
            #pragma unroll
            for (int q = 0; q < 4; q++)
                acc[i][j][q] = 0.f;

    const int NCH = HID / 32;   // 64

    auto issue = [&](int c, int buf) {
        uint32_t sb = ub + buf * STB;
        #pragma unroll
        for (int r = 0; r < 2; r++) {
            int row = rowL[r], qd = qdL[r];
            int brow = row;
            if (ropePerm) {
                int gg = row >> 5, ss = row & 31;
                brow = (ss < 16) ? gg*16 + ss : 64 + gg*16 + (ss - 16);
            }
            uint32_t so = (uint32_t)(row * SPAD + qd * 8) * 2;
            size_t   goA = (size_t)row  * HID + (size_t)c * 32 + qd * 8;
            size_t   goB = (size_t)brow * HID + (size_t)c * 32 + qd * 8;
            cpa16(sb + so,           pA + goA);
            cpa16(sb + ARR_B + so,   pBh + goB);
            if (NPROD == 2) cpa16(sb + 2*ARR_B + so, pBl + goB);
        }
        CP_COMMIT();
    };

    issue(0, 0);
    issue(1, 1);

    int buf = 0;   // buffer holding chunk c
    for (int c = 0; c < NCH; c++) {
        if (c + 1 < NCH) CP_WAIT1(); else CP_WAIT0();
        __syncthreads();
        if (c + 2 < NCH) {
            int nb = buf - 1; if (nb < 0) nb += 3;   // (c+2) % 3
            issue(c + 2, nb);
        }

        const uint32_t sb  = ub + buf * STB;
        const uint32_t uA  = sb;
        const uint32_t uBh = sb + ARR_B;
        const uint32_t uBl = sb + 2*ARR_B;

        #pragma unroll
        for (int kh = 0; kh < 2; kh++) {
            uint32_t ah[4][4], bh[2][4], bl[2][4];
            #pragma unroll
            for (int mt = 0; mt < 4; mt++) {
                uint32_t off = (uint32_t)((wm*64 + mt*16 + lrow) * SPAD + kh*16 + lcol*8) * 2;
                ldm4(ah[mt], uA + off);
            }
            #pragma unroll
            for (int n2 = 0; n2 < 2; n2++) {
                uint32_t off = (uint32_t)((wn*32 + n2*16 + lrow) * SPAD + kh*16 + lcol*8) * 2;
                ldm4(bh[n2], uBh + off);
                if (NPROD == 2) ldm4(bl[n2], uBl + off);
            }
            #pragma unroll
            for (int mt = 0; mt < 4; mt++)
                #pragma unroll
                for (int nt = 0; nt < 4; nt++) {
                    int n2 = nt >> 1, hb = nt & 1;
                    mma16816(acc[mt][nt], ah[mt], bh[n2][hb], bh[n2][hb+2]);
                    if (NPROD == 2)
                        mma16816(acc[mt][nt], ah[mt], bl[n2][hb], bl[n2][hb+2]);
                }
        }
        buf++; if (buf == 3) buf = 0;
    }
}

// ---------------------------------------------------------------------------
// Fused QKV projection launch. grid (48, 32):
//   widx = bx>>4: 0 -> Q (1-product + RoPE), 1 -> K (same), 2 -> V (2-product).
// ---------------------------------------------------------------------------
__global__ __launch_bounds__(256)
void mma_gemm_qkv(const h16* __restrict__ xh,
                  const h16* __restrict__ whb, const h16* __restrict__ wlb)
{
    extern __shared__ char dsm[];
    const uint32_t ub = smem_u32(dsm);

    const int t    = threadIdx.x;
    const int wid  = t >> 5;
    const int lane = t & 31;
    const int m0   = blockIdx.y << 7;
    const int wm   = wid & 1;
    const int wn   = wid >> 1;
    const int widx = blockIdx.x >> 4;
    const int n0   = (blockIdx.x & 15) << 7;
    const int h    = n0 >> 7;

    const h16* pA  = xh + (size_t)m0 * HID;
    const h16* pBh = whb + (size_t)widx * HID * HID + (size_t)n0 * HID;
    const h16* pBl = wlb + (size_t)widx * HID * HID + (size_t)n0 * HID;

    float acc[4][4][4];
    const int rbase = wm*64 + (lane >> 2);

    if (widx < 2) {
        gemm_core<1>(pA, pBh, nullptr, ub, true, acc);
        // RoPE epilogue, write single fp16 bhsd
        h16* outp = (widx == 0) ? g_Qf : g_Kf;
        const int dd0 = wn*16 + 2*(lane & 3);
        #pragma unroll
        for (int mt = 0; mt < 4; mt++)
            #pragma unroll
            for (int ntp = 0; ntp < 2; ntp++) {
                int d = dd0 + ntp*8;
                #pragma unroll
                for (int rr = 0; rr < 2; rr++) {
                    int r0 = m0 + rbase + mt*16 + rr*8;
                    int b  = r0 >> 11;
                    int s  = r0 & (SEQ - 1);
                    const float2* trow = g_cs + (size_t)s * DHEAD;
                    float2 cs1a = trow[d],      cs1b = trow[d+1];
                    float2 cs2a = trow[d+64],   cs2b = trow[d+65];
                    float x1a = acc[mt][ntp][rr*2+0],   x1b = acc[mt][ntp][rr*2+1];
                    float x2a = acc[mt][ntp+2][rr*2+0], x2b = acc[mt][ntp+2][rr*2+1];
                    float y1a = x1a*cs1a.x - x2a*cs1a.y;
                    float y1b = x1b*cs1b.x - x2b*cs1b.y;
                    float y2a = x2a*cs2a.x + x1a*cs2a.y;
                    float y2b = x2b*cs2b.x + x1b*cs2b.y;
                    size_t base = (((size_t)(b*NHEAD + h))*SEQ + s)*DHEAD;
                    *(uint32_t*)&outp[base + d] =
                        packh2(__float2half_rn(y1a), __float2half_rn(y1b));
                    *(uint32_t*)&outp[base + d + 64] =
                        packh2(__float2half_rn(y2a), __float2half_rn(y2b));
                }
            }
    } else {
        gemm_core<2>(pA, pBh, pBl, ub, false, acc);
        // V epilogue: h16 hi/lo bhsd (V tensor stays exact for PV)
        const int cbase = wn*32 + 2*(lane & 3);
        #pragma unroll
        for (int mt = 0; mt < 4; mt++)
            #pragma unroll
            for (int nt = 0; nt < 4; nt++) {
                int r0 = m0 + rbase + mt*16;
                int b  = r0 >> 11;
                int s  = r0 & (SEQ - 1);
                int d  = cbase + nt*8;
                size_t base = (((size_t)(b*NHEAD + h))*SEQ + s)*DHEAD + d;
                uint32_t hp, lp;
                split2packh(acc[mt][nt][0], acc[mt][nt][1], hp, lp);
                *(uint32_t*)&g_Vh[base] = hp;
                *(uint32_t*)&g_Vl[base] = lp;
                split2packh(acc[mt][nt][2], acc[mt][nt][3], hp, lp);
                *(uint32_t*)&g_Vh[base + 8*DHEAD] = hp;
                *(uint32_t*)&g_Vl[base + 8*DHEAD] = lp;
            }
    }
}

// ---------------------------------------------------------------------------
// Final O projection: 2-product (ctx single, Wo hi/lo), fp32 output.
// ---------------------------------------------------------------------------
__global__ __launch_bounds__(256)
void mma_gemm_o(const h16* __restrict__ ch,
                const h16* __restrict__ wh, const h16* __restrict__ wl,
                float* __restrict__ Cout)
{
    extern __shared__ char dsm[];
    const uint32_t ub = smem_u32(dsm);

    const int t    = threadIdx.x;
    const int wid  = t >> 5;
    const int lane = t & 31;
    const int m0   = blockIdx.y << 7;
    const int n0   = blockIdx.x << 7;
    const int wm   = wid & 1;
    const int wn   = wid >> 1;

    float acc[4][4][4];
    gemm_core<2>(ch + (size_t)m0 * HID,
                 wh + (size_t)n0 * HID, wl + (size_t)n0 * HID,
                 ub, false, acc);

    const int rbase = wm*64 + (lane >> 2);
    const int cbase = wn*32 + 2*(lane & 3);
    #pragma unroll
    for (int mt = 0; mt < 4; mt++)
        #pragma unroll
        for (int nt = 0; nt < 4; nt++) {
            int r0 = m0 + rbase + mt*16;
            int cc = n0 + cbase + nt*8;
            *(float2*)&Cout[(size_t)r0 * HID + cc]       = make_float2(acc[mt][nt][0], acc[mt][nt][1]);
            *(float2*)&Cout[(size_t)(r0 + 8) * HID + cc] = make_float2(acc[mt][nt][2], acc[mt][nt][3]);
        }
}

// ---------------------------------------------------------------------------
// Flash attention: BK=32, K/V cp.async 3-stage pipeline, 2 CTAs/SM.
// Warp owns 16 q-rows x full BK; P in registers; intra-warp softmax;
// warp-vote skip of O-rescale when running max is unchanged.
// Epilogue writes ctx as SINGLE fp16.
// ---------------------------------------------------------------------------
#define BQ 128
#define BK 32
#define QSTR 136
#define KSTR 136
#define QARR (128*QSTR*2)        // 34816
#define KARR (32*KSTR*2)         // 8704 per KV array
#define KVSTAGE (3*KARR)         // 26112
#define OFF_KV QARR
#define FLASH_SMEM (QARR + 3*KVSTAGE)   // 113152

__global__ __launch_bounds__(256, 2)
void flash_mma(const float* __restrict__ mask, const float* __restrict__ alibi)
{
    extern __shared__ char sm[];
    const uint32_t ub = smem_u32(sm);
    const uint32_t uQ = ub;
    h16* sQ = (h16*)sm;

    const int t    = threadIdx.x;
    const int lane = t & 31;
    const int wid  = t >> 5;
    const int qb   = blockIdx.x;
    const int bhid = blockIdx.y;
    const int h    = bhid & (NHEAD - 1);
    const int b    = bhid >> 4;
    const int qi0  = qb * BQ;
    const size_t hbase = (size_t)bhid * SEQ * DHEAD;

    const int lrow = lane & 15, lcol = lane >> 4;
    const int g = lane >> 2, tq = lane & 3;
    const float SCALE = 0.08838834764831845f;  // 1/sqrt(128)

    // Q tile load (sync stores)
    #pragma unroll
    for (int rep = 0; rep < 8; rep++) {
        int u = t + rep * 256;
        int row = u >> 4, c8 = (u & 15) * 8;
        *(uint4*)&sQ[row*QSTR + c8] =
            *(const uint4*)(g_Qf + hbase + (size_t)(qi0 + row) * DHEAD + c8);
    }

    // KV async stage loader: K single, V hi/lo (32 rows each)
    auto issueKV = [&](int kt, int buf) {
        uint32_t sb = ub + OFF_KV + buf * KVSTAGE;
        const int kj0 = kt * BK;
        #pragma unroll
        for (int rep = 0; rep < 2; rep++) {
            int u = t + rep * 256;
            int row = u >> 4, c8 = (u & 15) * 8;
            uint32_t so = (uint32_t)(row * KSTR + c8) * 2;
            size_t   go = hbase + (size_t)(kj0 + row) * DHEAD + c8;
            cpa16(sb + so,          g_Kf + go);
            cpa16(sb + KARR + so,   g_Vh + go);
            cpa16(sb + 2*KARR + so, g_Vl + go);
        }
        CP_COMMIT();
    };
    issueKV(0, 0);
    issueKV(1, 1);

    float o[16][4];
    #pragma unroll
    for (int nt = 0; nt < 16; nt++)
        #pragma unroll
        for (int q = 0; q < 4; q++)
            o[nt][q] = 0.f;
    float m0r = -1e30f, m8r = -1e30f, l0r = 0.f, l8r = 0.f;
    const int r0g = qi0 + wid*16 + g;
    const int NKT = SEQ / BK;   // 64

    int buf = 0;
    for (int kt = 0; kt < NKT; kt++) {
        const int kj0 = kt * BK;
        if (kt + 1 < NKT) CP_WAIT1(); else CP_WAIT0();
        __syncthreads();
        if (kt + 2 < NKT) {
            int nb = buf - 1; if (nb < 0) nb += 3;
            issueKV(kt + 2, nb);
        }

        const uint32_t sb  = ub + OFF_KV + buf * KVSTAGE;
        const uint32_t uK  = sb;
        const uint32_t uVh = sb + KARR, uVl = sb + 2*KARR;

        // ---- S = Q K^T : warp tile 16 x 32, single product ----
        float sacc[4][4];
        #pragma unroll
        for (int nt = 0; nt < 4; nt++)
            #pragma unroll
            for (int q = 0; q < 4; q++)
                sacc[nt][q] = 0.f;

        #pragma unroll
        for (int kk = 0; kk < 8; kk++) {
            uint32_t qa[4], kb[2][4];
            uint32_t qoff = (uint32_t)((wid*16 + lrow)*QSTR + kk*16 + lcol*8) * 2;
            ldm4(qa, uQ + qoff);
            #pragma unroll
            for (int n2 = 0; n2 < 2; n2++) {
                uint32_t koff = (uint32_t)((n2*16 + lrow)*KSTR + kk*16 + lcol*8) * 2;
                ldm4(kb[n2], uK + koff);
            }
            #pragma unroll
            for (int nt = 0; nt < 4; nt++) {
                int n2 = nt >> 1, hb = nt & 1;
                mma16816(sacc[nt], qa, kb[n2][hb], kb[n2][hb+2]);
            }
        }

        // ---- scale + mask + alibi, row max (intra-warp only) ----
        float rmax0 = -1e30f, rmax8 = -1e30f;
        #pragma unroll
        for (int nt = 0; nt < 4; nt++) {
            int col = kj0 + nt*8 + 2*tq;
            float2 av  = *(const float2*)(alibi + (size_t)h * SEQ + col);
            float2 mv0 = *(const float2*)(mask + (size_t)r0g * SEQ + col);
            float2 mv1 = *(const float2*)(mask + (size_t)(r0g + 8) * SEQ + col);
            sacc[nt][0] = fmaf(sacc[nt][0], SCALE, mv0.x + av.x);
            sacc[nt][1] = fmaf(sacc[nt][1], SCALE, mv0.y + av.y);
            sacc[nt][2] = fmaf(sacc[nt][2], SCALE, mv1.x + av.x);
            sacc[nt][3] = fmaf(sacc[nt][3], SCALE, mv1.y + av.y);
            rmax0 = fmaxf(rmax0, fmaxf(sacc[nt][0], sacc[nt][1]));
            rmax8 = fmaxf(rmax8, fmaxf(sacc[nt][2], sacc[nt][3]));
        }
        #pragma unroll
        for (int off = 1; off <= 2; off <<= 1) {
            rmax0 = fmaxf(rmax0, __shfl_xor_sync(0xffffffffu, rmax0, off));
            rmax8 = fmaxf(rmax8, __shfl_xor_sync(0xffffffffu, rmax8, off));
        }

        float nm0 = fmaxf(m0r, rmax0), nm8 = fmaxf(m8r, rmax8);
        float c0 = __expf(m0r - nm0),  c8 = __expf(m8r - nm8);
        m0r = nm0; m8r = nm8;

        // ---- exp + pack P fragments (single fp16) ----
        float rs0 = 0.f, rs8 = 0.f;
        uint32_t ph[2][4];
        #pragma unroll
        for (int kk = 0; kk < 2; kk++) {
            #pragma unroll
            for (int half = 0; half < 2; half++) {
                int nt = 2*kk + half;
                float p0 = __expf(sacc[nt][0] - nm0);
                float p1 = __expf(sacc[nt][1] - nm0);
                float p2 = __expf(sacc[nt][2] - nm8);
                float p3 = __expf(sacc[nt][3] - nm8);
                rs0 += p0 + p1; rs8 += p2 + p3;
                ph[kk][half*2+0] = packh2(__float2half_rn(p0), __float2half_rn(p1));
                ph[kk][half*2+1] = packh2(__float2half_rn(p2), __float2half_rn(p3));
            }
        }
        #pragma unroll
        for (int off = 1; off <= 2; off <<= 1) {
            rs0 += __shfl_xor_sync(0xffffffffu, rs0, off);
            rs8 += __shfl_xor_sync(0xffffffffu, rs8, off);
        }
        l0r = l0r * c0 + rs0;
        l8r = l8r * c8 + rs8;

        // ---- rescale O (skip when max unchanged across whole warp) ----
        bool need = (c0 != 1.0f) || (c8 != 1.0f);
        if (__any_sync(0xffffffffu, need)) {
            #pragma unroll
            for (int nt = 0; nt < 16; nt++) {
                o[nt][0] *= c0; o[nt][1] *= c0;
                o[nt][2] *= c8; o[nt][3] *= c8;
            }
        }

        // ---- O += P (Vh + Vl) : 2-product ----
        #pragma unroll
        for (int kk = 0; kk < 2; kk++) {
            #pragma unroll
            for (int dd = 0; dd < 8; dd++) {
                uint32_t vh_[4], vl_[4];
                uint32_t voff = (uint32_t)((kk*16 + lrow)*KSTR + dd*16 + lcol*8) * 2;
                ldm4t(vh_, uVh + voff);
                ldm4t(vl_, uVl + voff);
                mma16816(o[dd*2+0], ph[kk], vh_[0], vh_[1]);
                mma16816(o[dd*2+0], ph[kk], vl_[0], vl_[1]);
                mma16816(o[dd*2+1], ph[kk], vh_[2], vh_[3]);
                mma16816(o[dd*2+1], ph[kk], vl_[2], vl_[3]);
            }
        }
        buf++; if (buf == 3) buf = 0;
    }

    // ---- epilogue: normalize, write ctx as single fp16 [tok][h*128+d] ----
    float inv0 = 1.f / l0r, inv8 = 1.f / l8r;
    size_t tok0 = ((size_t)(b*SEQ + qi0 + wid*16 + g)) * HID + h * DHEAD;
    size_t tok8 = tok0 + (size_t)8 * HID;
    #pragma unroll
    for (int nt = 0; nt < 16; nt++) {
        int d = nt*8 + 2*tq;
        *(uint32_t*)&g_ch[tok0 + d] =
            packh2(__float2half_rn(o[nt][0]*inv0), __float2half_rn(o[nt][1]*inv0));
        *(uint32_t*)&g_ch[tok8 + d] =
            packh2(__float2half_rn(o[nt][2]*inv8), __float2half_rn(o[nt][3]*inv8));
    }
}

// ---------------------------------------------------------------------------
extern "C" void kernel_launch(void* const* d_in, const int* in_sizes, int n_in,
                              void* d_out, int out_size)
{
    const float* x     = (const float*)d_in[0];
    const float* mask  = (const float*)d_in[1];
    const float* alibi = (const float*)d_in[2];
    const float* freqs = (const float*)d_in[3];
    const float* W[4]  = { (const float*)d_in[4], (const float*)d_in[5],
                           (const float*)d_in[6], (const float*)d_in[7] };
    float* out = (float*)d_out;
    (void)in_sizes; (void)n_in; (void)out_size;

    cudaFuncSetAttribute(flash_mma,
                         cudaFuncAttributeMaxDynamicSharedMemorySize, FLASH_SMEM);
    cudaFuncSetAttribute(mma_gemm_qkv,
                         cudaFuncAttributeMaxDynamicSharedMemorySize, GEMM_SMEM);
    cudaFuncSetAttribute(mma_gemm_o,
                         cudaFuncAttributeMaxDynamicSharedMemorySize, GEMM_SMEM);

    h16 *xh, *ch, *whbase, *wlbase;
    cudaGetSymbolAddress((void**)&xh, g_xh);
    cudaGetSymbolAddress((void**)&ch, g_ch);
    cudaGetSymbolAddress((void**)&whbase, g_wh);
    cudaGetSymbolAddress((void**)&wlbase, g_wl);

    {
        int total = (NTOK * HID + 4 * HID * HID) / 4;
        split_all<<<(total + 255) / 256, 256>>>(
            x, W[0], W[1], W[2], W[3], xh, whbase, wlbase);
        build_cs<<<(SEQ * DHEAD) / 256, 256>>>(freqs);
    }

    // Fused Q/K (1-product + RoPE) and V (2-product) projections
    mma_gemm_qkv<<<dim3(48, NTOK/128), 256, GEMM_SMEM>>>(xh, whbase, wlbase);

    flash_mma<<<dim3(SEQ/BQ, NBATCH*NHEAD), 256, FLASH_SMEM>>>(mask, alibi);

    // O projection: 2-product (ctx single, Wo hi/lo)
    mma_gemm_o<<<dim3(16, NTOK/128), 256, GEMM_SMEM>>>(
        ch, whbase + 3*(size_t)HID*HID, wlbase + 3*(size_t)HID*HID, out);
}

// round 13
// speedup vs baseline: 1.0315x; 1.0315x over previous
#include <cuda_runtime.h>
#include <cuda_fp16.h>
#include <math.h>
#include <cstdint>

typedef __half h16;

// Problem constants
#define NBATCH 2
#define SEQ    2048
#define NHEAD  16
#define DHEAD  128
#define HID    2048
#define NTOK   4096   // NBATCH*SEQ

// Scratch (device globals — no runtime allocation allowed)
__device__ h16 g_Qf[NBATCH*NHEAD*SEQ*DHEAD];    // post-RoPE, single fp16
__device__ h16 g_Kf[NBATCH*NHEAD*SEQ*DHEAD];
__device__ h16 g_Vh[NBATCH*NHEAD*SEQ*DHEAD];    // V hi/lo fp16 (direct path)
__device__ h16 g_Vl[NBATCH*NHEAD*SEQ*DHEAD];

__device__ h16 g_xh[(size_t)NTOK*HID];          // x single fp16
__device__ h16 g_ch[(size_t)NTOK*HID];          // ctx single fp16 (flash output)
__device__ h16 g_wh[4][(size_t)HID*HID];        // weights hi/lo
__device__ h16 g_wl[4][(size_t)HID*HID];

__device__ float2 g_cs[SEQ*DHEAD];              // (cos, sin) of freqs
__device__ h16 g_maskh[(size_t)SEQ*SEQ];        // mask fp16
__device__ h16 g_alh[NHEAD*SEQ];                // alibi fp16

// ---------------------------------------------------------------------------
// helpers
// ---------------------------------------------------------------------------
__device__ __forceinline__ uint32_t smem_u32(const void* p) {
    uint32_t a;
    asm("{ .reg .u64 t; cvta.to.shared.u64 t, %1; cvt.u32.u64 %0, t; }"
        : "=r"(a) : "l"(p));
    return a;
}
__device__ __forceinline__ void ldm4(uint32_t* r, uint32_t addr) {
    asm volatile("ldmatrix.sync.aligned.m8n8.x4.shared.b16 {%0,%1,%2,%3},[%4];"
                 : "=r"(r[0]), "=r"(r[1]), "=r"(r[2]), "=r"(r[3]) : "r"(addr));
}
__device__ __forceinline__ void ldm4t(uint32_t* r, uint32_t addr) {
    asm volatile("ldmatrix.sync.aligned.m8n8.x4.trans.shared.b16 {%0,%1,%2,%3},[%4];"
                 : "=r"(r[0]), "=r"(r[1]), "=r"(r[2]), "=r"(r[3]) : "r"(addr));
}
__device__ __forceinline__ void mma16816(float* d, const uint32_t* a,
                                         uint32_t b0, uint32_t b1) {
    asm volatile(
        "mma.sync.aligned.m16n8k16.row.col.f32.f16.f16.f32 "
        "{%0,%1,%2,%3},{%4,%5,%6,%7},{%8,%9},{%0,%1,%2,%3};"
        : "+f"(d[0]), "+f"(d[1]), "+f"(d[2]), "+f"(d[3])
        : "r"(a[0]), "r"(a[1]), "r"(a[2]), "r"(a[3]), "r"(b0), "r"(b1));
}
__device__ __forceinline__ uint32_t packh2(h16 a, h16 b) {
    return ((uint32_t)__half_as_ushort(b) << 16) | __half_as_ushort(a);
}
__device__ __forceinline__ void split1h(float v, h16& h, h16& l) {
    h = __float2half_rn(v);
    l = __float2half_rn(v - __half2float(h));
}
__device__ __forceinline__ void split2packh(float a, float b,
                                            uint32_t& hp, uint32_t& lp) {
    h16 ha, la, hb, lb;
    split1h(a, ha, la);
    split1h(b, hb, lb);
    hp = packh2(ha, hb);
    lp = packh2(la, lb);
}
__device__ __forceinline__ void cpa16(uint32_t s, const void* g) {
    asm volatile("cp.async.cg.shared.global [%0], [%1], 16;" :: "r"(s), "l"(g));
}
#define CP_COMMIT() asm volatile("cp.async.commit_group;" ::: "memory")
#define CP_WAIT0()  asm volatile("cp.async.wait_group 0;" ::: "memory")

// ---------------------------------------------------------------------------
// prep: cos/sin table + fp16 alibi
// ---------------------------------------------------------------------------
__global__ __launch_bounds__(256)
void build_cs(const float* __restrict__ freqs, const float* __restrict__ alibi)
{
    int i = blockIdx.x * 256 + threadIdx.x;   // SEQ*DHEAD = 262144
    float f = freqs[i];
    g_cs[i] = make_float2(cosf(f), sinf(f));
    if (i < NHEAD * SEQ) g_alh[i] = __float2half_rn(alibi[i]);
}

// mask fp32 -> fp16 (4.19M elements, 4 per thread)
__global__ __launch_bounds__(256)
void build_maskh(const float* __restrict__ mask)
{
    int i = blockIdx.x * 256 + threadIdx.x;   // SEQ*SEQ/4 = 1M
    float4 v = ((const float4*)mask)[i];
    ((uint2*)g_maskh)[i] = make_uint2(
        packh2(__float2half_rn(v.x), __float2half_rn(v.y)),
        packh2(__float2half_rn(v.z), __float2half_rn(v.w)));
}

// ---------------------------------------------------------------------------
// Fused split: x -> single fp16; 4 weights -> fp16 hi + lo. One launch.
// ---------------------------------------------------------------------------
__global__ __launch_bounds__(256)
void split_all(const float* __restrict__ x,
               const float* __restrict__ w0, const float* __restrict__ w1,
               const float* __restrict__ w2, const float* __restrict__ w3,
               h16* __restrict__ xh,
               h16* __restrict__ whb, h16* __restrict__ wlb)
{
    const int XQ = NTOK * HID / 4;
    const int WQ = HID * HID / 4;
    int i = blockIdx.x * 256 + threadIdx.x;
    if (i < XQ) {
        float4 v = ((const float4*)x)[i];
        ((uint2*)xh)[i] = make_uint2(
            packh2(__float2half_rn(v.x), __float2half_rn(v.y)),
            packh2(__float2half_rn(v.z), __float2half_rn(v.w)));
        return;
    }
    int j = i - XQ;
    int widx = j >> 20;
    int off = j & (WQ - 1);
    const float* src = (widx == 0) ? w0 : (widx == 1) ? w1 : (widx == 2) ? w2 : w3;
    h16* dh = whb + (size_t)widx * HID * HID;
    h16* dl = wlb + (size_t)widx * HID * HID;
    float4 v = ((const float4*)src)[off];
    float vv[4] = {v.x, v.y, v.z, v.w};
    h16 hh[4], ll[4];
    #pragma unroll
    for (int q = 0; q < 4; q++) split1h(vv[q], hh[q], ll[q]);
    ((uint2*)dh)[off] = make_uint2(packh2(hh[0], hh[1]), packh2(hh[2], hh[3]));
    ((uint2*)dl)[off] = make_uint2(packh2(ll[0], ll[1]), packh2(ll[2], ll[3]));
}

// ---------------------------------------------------------------------------
// GEMM core: 128x128 tile, cp.async 2-stage, NPROD in {1,2}.  (R11 config)
// ---------------------------------------------------------------------------
#define SPAD 40
#define ARR_B   (128*SPAD*2)          // 10240
#define GEMM_SMEM (2 * 3 * ARR_B)     // 61440 -> 3 CTAs/SM

template<int NPROD>
__device__ __forceinline__ void gemm_core(
    const h16* __restrict__ pA,
    const h16* __restrict__ pBh, const h16* __restrict__ pBl,
    uint32_t ub, bool ropePerm, float acc[4][4][4])
{
    constexpr int STB = (NPROD == 2 ? 3 : 2) * ARR_B;
    const int t    = threadIdx.x;
    const int wid  = t >> 5;
    const int lane = t & 31;
    const int wm   = wid & 1;
    const int wn   = wid >> 1;
    const int lrow = lane & 15, lcol = lane >> 4;

    int rowL[2], qdL[2];
    #pragma unroll
    for (int r = 0; r < 2; r++) {
        int u = t + (r << 8);
        rowL[r] = u >> 2;
        qdL[r]  = u & 3;
    }

    #pragma unroll
    for (int i = 0; i < 4; i++)
        #pragma unroll
        for (int j = 0; j < 4; j++)
            #pragma unroll
            for (int q = 0; q < 4; q++)
                acc[i][j][q] = 0.f;

    const int NCH = HID / 32;

    auto issue = [&](int c, int buf) {
        uint32_t sb = ub + buf * STB;
        #pragma unroll
        for (int r = 0; r < 2; r++) {
            int row = rowL[r], qd = qdL[r];
            int brow = row;
            if (ropePerm) {
                int gg = row >> 5, ss = row & 31;
                brow = (ss < 16) ? gg*16 + ss : 64 + gg*16 + (ss - 16);
            }
            uint32_t so = (uint32_t)(row * SPAD + qd * 8) * 2;
            size_t   goA = (size_t)row  * HID + (size_t)c * 32 + qd * 8;
            size_t   goB = (size_t)brow * HID + (size_t)c * 32 + qd * 8;
            cpa16(sb + so,           pA + goA);
            cpa16(sb + ARR_B + so,   pBh + goB);
            if (NPROD == 2) cpa16(sb + 2*ARR_B + so, pBl + goB);
        }
        CP_COMMIT();
    };

    issue(0, 0);

    for (int c = 0; c < NCH; c++) {
        CP_WAIT0();
        __syncthreads();
        if (c + 1 < NCH) issue(c + 1, (c + 1) & 1);

        const uint32_t sb  = ub + (c & 1) * STB;
        const uint32_t uA  = sb;
        const uint32_t uBh = sb + ARR_B;
        const uint32_t uBl = sb + 2*ARR_B;

        #pragma unroll
        for (int kh = 0; kh < 2; kh++) {
            uint32_t ah[4][4], bh[2][4], bl[2][4];
            #pragma unroll
            for (int mt = 0; mt < 4; mt++) {
                uint32_t off = (uint32_t)((wm*64 + mt*16 + lrow) * SPAD + kh*16 + lcol*8) * 2;
                ldm4(ah[mt], uA + off);
            }
            #pragma unroll
            for (int n2 = 0; n2 < 2; n2++) {
                uint32_t off = (uint32_t)((wn*32 + n2*16 + lrow) * SPAD + kh*16 + lcol*8) * 2;
                ldm4(bh[n2], uBh + off);
                if (NPROD == 2) ldm4(bl[n2], uBl + off);
            }
            #pragma unroll
            for (int mt = 0; mt < 4; mt++)
                #pragma unroll
                for (int nt = 0; nt < 4; nt++) {
                    int n2 = nt >> 1, hb = nt & 1;
                    mma16816(acc[mt][nt], ah[mt], bh[n2][hb], bh[n2][hb+2]);
                    if (NPROD == 2)
                        mma16816(acc[mt][nt], ah[mt], bl[n2][hb], bl[n2][hb+2]);
                }
        }
    }
}

// ---------------------------------------------------------------------------
// Fused QKV projection launch. grid (48, 32).
// ---------------------------------------------------------------------------
__global__ __launch_bounds__(256)
void mma_gemm_qkv(const h16* __restrict__ xh,
                  const h16* __restrict__ whb, const h16* __restrict__ wlb)
{
    extern __shared__ char dsm[];
    const uint32_t ub = smem_u32(dsm);

    const int t    = threadIdx.x;
    const int wid  = t >> 5;
    const int lane = t & 31;
    const int m0   = blockIdx.y << 7;
    const int wm   = wid & 1;
    const int wn   = wid >> 1;
    const int widx = blockIdx.x >> 4;
    const int n0   = (blockIdx.x & 15) << 7;
    const int h    = n0 >> 7;

    const h16* pA  = xh + (size_t)m0 * HID;
    const h16* pBh = whb + (size_t)widx * HID * HID + (size_t)n0 * HID;
    const h16* pBl = wlb + (size_t)widx * HID * HID + (size_t)n0 * HID;

    float acc[4][4][4];
    const int rbase = wm*64 + (lane >> 2);

    if (widx < 2) {
        gemm_core<1>(pA, pBh, nullptr, ub, true, acc);
        h16* outp = (widx == 0) ? g_Qf : g_Kf;
        const int dd0 = wn*16 + 2*(lane & 3);
        #pragma unroll
        for (int mt = 0; mt < 4; mt++)
            #pragma unroll
            for (int ntp = 0; ntp < 2; ntp++) {
                int d = dd0 + ntp*8;
                #pragma unroll
                for (int rr = 0; rr < 2; rr++) {
                    int r0 = m0 + rbase + mt*16 + rr*8;
                    int b  = r0 >> 11;
                    int s  = r0 & (SEQ - 1);
                    const float2* trow = g_cs + (size_t)s * DHEAD;
                    float2 cs1a = trow[d],      cs1b = trow[d+1];
                    float2 cs2a = trow[d+64],   cs2b = trow[d+65];
                    float x1a = acc[mt][ntp][rr*2+0],   x1b = acc[mt][ntp][rr*2+1];
                    float x2a = acc[mt][ntp+2][rr*2+0], x2b = acc[mt][ntp+2][rr*2+1];
                    float y1a = x1a*cs1a.x - x2a*cs1a.y;
                    float y1b = x1b*cs1b.x - x2b*cs1b.y;
                    float y2a = x2a*cs2a.x + x1a*cs2a.y;
                    float y2b = x2b*cs2b.x + x1b*cs2b.y;
                    size_t base = (((size_t)(b*NHEAD + h))*SEQ + s)*DHEAD;
                    *(uint32_t*)&outp[base + d] =
                        packh2(__float2half_rn(y1a), __float2half_rn(y1b));
                    *(uint32_t*)&outp[base + d + 64] =
                        packh2(__float2half_rn(y2a), __float2half_rn(y2b));
                }
            }
    } else {
        gemm_core<2>(pA, pBh, pBl, ub, false, acc);
        const int cbase = wn*32 + 2*(lane & 3);
        #pragma unroll
        for (int mt = 0; mt < 4; mt++)
            #pragma unroll
            for (int nt = 0; nt < 4; nt++) {
                int r0 = m0 + rbase + mt*16;
                int b  = r0 >> 11;
                int s  = r0 & (SEQ - 1);
                int d  = cbase + nt*8;
                size_t base = (((size_t)(b*NHEAD + h))*SEQ + s)*DHEAD + d;
                uint32_t hp, lp;
                split2packh(acc[mt][nt][0], acc[mt][nt][1], hp, lp);
                *(uint32_t*)&g_Vh[base] = hp;
                *(uint32_t*)&g_Vl[base] = lp;
                split2packh(acc[mt][nt][2], acc[mt][nt][3], hp, lp);
                *(uint32_t*)&g_Vh[base + 8*DHEAD] = hp;
                *(uint32_t*)&g_Vl[base + 8*DHEAD] = lp;
            }
    }
}

// ---------------------------------------------------------------------------
// Final O projection: 2-product (ctx single, Wo hi/lo), fp32 output.
// ---------------------------------------------------------------------------
__global__ __launch_bounds__(256)
void mma_gemm_o(const h16* __restrict__ ch,
                const h16* __restrict__ wh, const h16* __restrict__ wl,
                float* __restrict__ Cout)
{
    extern __shared__ char dsm[];
    const uint32_t ub = smem_u32(dsm);

    const int t    = threadIdx.x;
    const int wid  = t >> 5;
    const int lane = t & 31;
    const int m0   = blockIdx.y << 7;
    const int n0   = blockIdx.x << 7;
    const int wm   = wid & 1;
    const int wn   = wid >> 1;

    float acc[4][4][4];
    gemm_core<2>(ch + (size_t)m0 * HID,
                 wh + (size_t)n0 * HID, wl + (size_t)n0 * HID,
                 ub, false, acc);

    const int rbase = wm*64 + (lane >> 2);
    const int cbase = wn*32 + 2*(lane & 3);
    #pragma unroll
    for (int mt = 0; mt < 4; mt++)
        #pragma unroll
        for (int nt = 0; nt < 4; nt++) {
            int r0 = m0 + rbase + mt*16;
            int cc = n0 + cbase + nt*8;
            *(float2*)&Cout[(size_t)r0 * HID + cc]       = make_float2(acc[mt][nt][0], acc[mt][nt][1]);
            *(float2*)&Cout[(size_t)(r0 + 8) * HID + cc] = make_float2(acc[mt][nt][2], acc[mt][nt][3]);
        }
}

// ---------------------------------------------------------------------------
// Flash attention (R11 config): BK=32, K/V cp.async 2-stage, 2 CTAs/SM.
// Bias (mask+alibi) read as fp16 — halves gmem bias traffic.
// ---------------------------------------------------------------------------
#define BQ 128
#define BK 32
#define QSTR 136
#define KSTR 136
#define QARR (128*QSTR*2)        // 34816
#define KARR (32*KSTR*2)         // 8704 per KV array
#define KVSTAGE (3*KARR)         // 26112
#define OFF_KV QARR
#define FLASH_SMEM (QARR + 2*KVSTAGE)   // 87040

__global__ __launch_bounds__(256, 2)
void flash_mma()
{
    extern __shared__ char sm[];
    const uint32_t ub = smem_u32(sm);
    const uint32_t uQ = ub;
    h16* sQ = (h16*)sm;

    const int t    = threadIdx.x;
    const int lane = t & 31;
    const int wid  = t >> 5;
    const int qb   = blockIdx.x;
    const int bhid = blockIdx.y;
    const int h    = bhid & (NHEAD - 1);
    const int b    = bhid >> 4;
    const int qi0  = qb * BQ;
    const size_t hbase = (size_t)bhid * SEQ * DHEAD;

    const int lrow = lane & 15, lcol = lane >> 4;
    const int g = lane >> 2, tq = lane & 3;
    const float SCALE = 0.08838834764831845f;  // 1/sqrt(128)

    // Q tile load (sync stores)
    #pragma unroll
    for (int rep = 0; rep < 8; rep++) {
        int u = t + rep * 256;
        int row = u >> 4, c8 = (u & 15) * 8;
        *(uint4*)&sQ[row*QSTR + c8] =
            *(const uint4*)(g_Qf + hbase + (size_t)(qi0 + row) * DHEAD + c8);
    }

    // KV async stage loader: K single, V hi/lo (32 rows each)
    auto issueKV = [&](int kt) {
        uint32_t sb = ub + OFF_KV + (kt & 1) * KVSTAGE;
        const int kj0 = kt * BK;
        #pragma unroll
        for (int rep = 0; rep < 2; rep++) {
            int u = t + rep * 256;
            int row = u >> 4, c8 = (u & 15) * 8;
            uint32_t so = (uint32_t)(row * KSTR + c8) * 2;
            size_t   go = hbase + (size_t)(kj0 + row) * DHEAD + c8;
            cpa16(sb + so,          g_Kf + go);
            cpa16(sb + KARR + so,   g_Vh + go);
            cpa16(sb + 2*KARR + so, g_Vl + go);
        }
        CP_COMMIT();
    };
    issueKV(0);

    float o[16][4];
    #pragma unroll
    for (int nt = 0; nt < 16; nt++)
        #pragma unroll
        for (int q = 0; q < 4; q++)
            o[nt][q] = 0.f;
    float m0r = -1e30f, m8r = -1e30f, l0r = 0.f, l8r = 0.f;
    const int r0g = qi0 + wid*16 + g;

    for (int kt = 0; kt < SEQ / BK; kt++) {
        const int kj0 = kt * BK;
        CP_WAIT0();
        __syncthreads();
        if (kt + 1 < SEQ / BK) issueKV(kt + 1);

        const uint32_t sb  = ub + OFF_KV + (kt & 1) * KVSTAGE;
        const uint32_t uK  = sb;
        const uint32_t uVh = sb + KARR, uVl = sb + 2*KARR;

        // ---- S = Q K^T : warp tile 16 x 32, single product ----
        float sacc[4][4];
        #pragma unroll
        for (int nt = 0; nt < 4; nt++)
            #pragma unroll
            for (int q = 0; q < 4; q++)
                sacc[nt][q] = 0.f;

        #pragma unroll
        for (int kk = 0; kk < 8; kk++) {
            uint32_t qa[4], kb[2][4];
            uint32_t qoff = (uint32_t)((wid*16 + lrow)*QSTR + kk*16 + lcol*8) * 2;
            ldm4(qa, uQ + qoff);
            #pragma unroll
            for (int n2 = 0; n2 < 2; n2++) {
                uint32_t koff = (uint32_t)((n2*16 + lrow)*KSTR + kk*16 + lcol*8) * 2;
                ldm4(kb[n2], uK + koff);
            }
            #pragma unroll
            for (int nt = 0; nt < 4; nt++) {
                int n2 = nt >> 1, hb = nt & 1;
                mma16816(sacc[nt], qa, kb[n2][hb], kb[n2][hb+2]);
            }
        }

        // ---- scale + fp16 bias (mask+alibi), row max (intra-warp only) ----
        float rmax0 = -1e30f, rmax8 = -1e30f;
        #pragma unroll
        for (int nt = 0; nt < 4; nt++) {
            int col = kj0 + nt*8 + 2*tq;
            float2 av  = __half22float2(*(const __half2*)(g_alh + (size_t)h * SEQ + col));
            float2 mv0 = __half22float2(*(const __half2*)(g_maskh + (size_t)r0g * SEQ + col));
            float2 mv1 = __half22float2(*(const __half2*)(g_maskh + (size_t)(r0g + 8) * SEQ + col));
            sacc[nt][0] = fmaf(sacc[nt][0], SCALE, mv0.x + av.x);
            sacc[nt][1] = fmaf(sacc[nt][1], SCALE, mv0.y + av.y);
            sacc[nt][2] = fmaf(sacc[nt][2], SCALE, mv1.x + av.x);
            sacc[nt][3] = fmaf(sacc[nt][3], SCALE, mv1.y + av.y);
            rmax0 = fmaxf(rmax0, fmaxf(sacc[nt][0], sacc[nt][1]));
            rmax8 = fmaxf(rmax8, fmaxf(sacc[nt][2], sacc[nt][3]));
        }
        #pragma unroll
        for (int off = 1; off <= 2; off <<= 1) {
            rmax0 = fmaxf(rmax0, __shfl_xor_sync(0xffffffffu, rmax0, off));
            rmax8 = fmaxf(rmax8, __shfl_xor_sync(0xffffffffu, rmax8, off));
        }

        float nm0 = fmaxf(m0r, rmax0), nm8 = fmaxf(m8r, rmax8);
        float c0 = __expf(m0r - nm0),  c8 = __expf(m8r - nm8);
        m0r = nm0; m8r = nm8;

        // ---- exp + pack P fragments (single fp16) ----
        float rs0 = 0.f, rs8 = 0.f;
        uint32_t ph[2][4];
        #pragma unroll
        for (int kk = 0; kk < 2; kk++) {
            #pragma unroll
            for (int half = 0; half < 2; half++) {
                int nt = 2*kk + half;
                float p0 = __expf(sacc[nt][0] - nm0);
                float p1 = __expf(sacc[nt][1] - nm0);
                float p2 = __expf(sacc[nt][2] - nm8);
                float p3 = __expf(sacc[nt][3] - nm8);
                rs0 += p0 + p1; rs8 += p2 + p3;
                ph[kk][half*2+0] = packh2(__float2half_rn(p0), __float2half_rn(p1));
                ph[kk][half*2+1] = packh2(__float2half_rn(p2), __float2half_rn(p3));
            }
        }
        #pragma unroll
        for (int off = 1; off <= 2; off <<= 1) {
            rs0 += __shfl_xor_sync(0xffffffffu, rs0, off);
            rs8 += __shfl_xor_sync(0xffffffffu, rs8, off);
        }
        l0r = l0r * c0 + rs0;
        l8r = l8r * c8 + rs8;

        // ---- rescale O ----
        #pragma unroll
        for (int nt = 0; nt < 16; nt++) {
            o[nt][0] *= c0; o[nt][1] *= c0;
            o[nt][2] *= c8; o[nt][3] *= c8;
        }

        // ---- O += P (Vh + Vl) : 2-product ----
        #pragma unroll
        for (int kk = 0; kk < 2; kk++) {
            #pragma unroll
            for (int dd = 0; dd < 8; dd++) {
                uint32_t vh_[4], vl_[4];
                uint32_t voff = (uint32_t)((kk*16 + lrow)*KSTR + dd*16 + lcol*8) * 2;
                ldm4t(vh_, uVh + voff);
                ldm4t(vl_, uVl + voff);
                mma16816(o[dd*2+0], ph[kk], vh_[0], vh_[1]);
                mma16816(o[dd*2+0], ph[kk], vl_[0], vl_[1]);
                mma16816(o[dd*2+1], ph[kk], vh_[2], vh_[3]);
                mma16816(o[dd*2+1], ph[kk], vl_[2], vl_[3]);
            }
        }
    }

    // ---- epilogue: normalize, write ctx as single fp16 [tok][h*128+d] ----
    float inv0 = 1.f / l0r, inv8 = 1.f / l8r;
    size_t tok0 = ((size_t)(b*SEQ + qi0 + wid*16 + g)) * HID + h * DHEAD;
    size_t tok8 = tok0 + (size_t)8 * HID;
    #pragma unroll
    for (int nt = 0; nt < 16; nt++) {
        int d = nt*8 + 2*tq;
        *(uint32_t*)&g_ch[tok0 + d] =
            packh2(__float2half_rn(o[nt][0]*inv0), __float2half_rn(o[nt][1]*inv0));
        *(uint32_t*)&g_ch[tok8 + d] =
            packh2(__float2half_rn(o[nt][2]*inv8), __float2half_rn(o[nt][3]*inv8));
    }
}

// ---------------------------------------------------------------------------
extern "C" void kernel_launch(void* const* d_in, const int* in_sizes, int n_in,
                              void* d_out, int out_size)
{
    const float* x     = (const float*)d_in[0];
    const float* mask  = (const float*)d_in[1];
    const float* alibi = (const float*)d_in[2];
    const float* freqs = (const float*)d_in[3];
    const float* W[4]  = { (const float*)d_in[4], (const float*)d_in[5],
                           (const float*)d_in[6], (const float*)d_in[7] };
    float* out = (float*)d_out;
    (void)in_sizes; (void)n_in; (void)out_size;

    cudaFuncSetAttribute(flash_mma,
                         cudaFuncAttributeMaxDynamicSharedMemorySize, FLASH_SMEM);
    cudaFuncSetAttribute(mma_gemm_qkv,
                         cudaFuncAttributeMaxDynamicSharedMemorySize, GEMM_SMEM);
    cudaFuncSetAttribute(mma_gemm_o,
                         cudaFuncAttributeMaxDynamicSharedMemorySize, GEMM_SMEM);

    h16 *xh, *ch, *whbase, *wlbase;
    cudaGetSymbolAddress((void**)&xh, g_xh);
    cudaGetSymbolAddress((void**)&ch, g_ch);
    cudaGetSymbolAddress((void**)&whbase, g_wh);
    cudaGetSymbolAddress((void**)&wlbase, g_wl);

    {
        int total = (NTOK * HID + 4 * HID * HID) / 4;
        split_all<<<(total + 255) / 256, 256>>>(
            x, W[0], W[1], W[2], W[3], xh, whbase, wlbase);
        build_cs<<<(SEQ * DHEAD) / 256, 256>>>(freqs, alibi);
        build_maskh<<<(SEQ * SEQ / 4) / 256, 256>>>(mask);
    }

    // Fused Q/K (1-product + RoPE) and V (2-product) projections
    mma_gemm_qkv<<<dim3(48, NTOK/128), 256, GEMM_SMEM>>>(xh, whbase, wlbase);

    flash_mma<<<dim3(SEQ/BQ, NBATCH*NHEAD), 256, FLASH_SMEM>>>();

    // O projection: 2-product (ctx single, Wo hi/lo)
    mma_gemm_o<<<dim3(16, NTOK/128), 256, GEMM_SMEM>>>(
        ch, whbase + 3*(size_t)HID*HID, wlbase + 3*(size_t)HID*HID, out);
}

// round 14
// speedup vs baseline: 1.0430x; 1.0111x over previous
#include <cuda_runtime.h>
#include <cuda_fp16.h>
#include <math.h>
#include <cstdint>

typedef __half h16;

// Problem constants
#define NBATCH 2
#define SEQ    2048
#define NHEAD  16
#define DHEAD  128
#define HID    2048
#define NTOK   4096   // NBATCH*SEQ

// Scratch (device globals — no runtime allocation allowed)
__device__ h16 g_Qf[NBATCH*NHEAD*SEQ*DHEAD];    // post-RoPE, single fp16
__device__ h16 g_Kf[NBATCH*NHEAD*SEQ*DHEAD];
__device__ h16 g_Vh[NBATCH*NHEAD*SEQ*DHEAD];    // V hi/lo fp16 (direct path)
__device__ h16 g_Vl[NBATCH*NHEAD*SEQ*DHEAD];

__device__ h16 g_xh[(size_t)NTOK*HID];          // x single fp16
__device__ h16 g_ch[(size_t)NTOK*HID];          // ctx single fp16 (flash output)
__device__ h16 g_wh[4][(size_t)HID*HID];        // weights hi/lo
__device__ h16 g_wl[4][(size_t)HID*HID];

__device__ float2 g_cs[SEQ*DHEAD];              // (cos, sin) of freqs

// ---------------------------------------------------------------------------
// helpers
// ---------------------------------------------------------------------------
__device__ __forceinline__ uint32_t smem_u32(const void* p) {
    uint32_t a;
    asm("{ .reg .u64 t; cvta.to.shared.u64 t, %1; cvt.u32.u64 %0, t; }"
        : "=r"(a) : "l"(p));
    return a;
}
__device__ __forceinline__ void ldm4(uint32_t* r, uint32_t addr) {
    asm volatile("ldmatrix.sync.aligned.m8n8.x4.shared.b16 {%0,%1,%2,%3},[%4];"
                 : "=r"(r[0]), "=r"(r[1]), "=r"(r[2]), "=r"(r[3]) : "r"(addr));
}
__device__ __forceinline__ void ldm4t(uint32_t* r, uint32_t addr) {
    asm volatile("ldmatrix.sync.aligned.m8n8.x4.trans.shared.b16 {%0,%1,%2,%3},[%4];"
                 : "=r"(r[0]), "=r"(r[1]), "=r"(r[2]), "=r"(r[3]) : "r"(addr));
}
__device__ __forceinline__ void mma16816(float* d, const uint32_t* a,
                                         uint32_t b0, uint32_t b1) {
    asm volatile(
        "mma.sync.aligned.m16n8k16.row.col.f32.f16.f16.f32 "
        "{%0,%1,%2,%3},{%4,%5,%6,%7},{%8,%9},{%0,%1,%2,%3};"
        : "+f"(d[0]), "+f"(d[1]), "+f"(d[2]), "+f"(d[3])
        : "r"(a[0]), "r"(a[1]), "r"(a[2]), "r"(a[3]), "r"(b0), "r"(b1));
}
__device__ __forceinline__ uint32_t packh2(h16 a, h16 b) {
    return ((uint32_t)__half_as_ushort(b) << 16) | __half_as_ushort(a);
}
__device__ __forceinline__ void split1h(float v, h16& h, h16& l) {
    h = __float2half_rn(v);
    l = __float2half_rn(v - __half2float(h));
}
__device__ __forceinline__ void split2packh(float a, float b,
                                            uint32_t& hp, uint32_t& lp) {
    h16 ha, la, hb, lb;
    split1h(a, ha, la);
    split1h(b, hb, lb);
    hp = packh2(ha, hb);
    lp = packh2(la, lb);
}
__device__ __forceinline__ void cpa16(uint32_t s, const void* g) {
    asm volatile("cp.async.cg.shared.global [%0], [%1], 16;" :: "r"(s), "l"(g));
}
#define CP_COMMIT() asm volatile("cp.async.commit_group;" ::: "memory")
#define CP_WAIT0()  asm volatile("cp.async.wait_group 0;" ::: "memory")

// ---------------------------------------------------------------------------
// cos/sin table from freqs
// ---------------------------------------------------------------------------
__global__ __launch_bounds__(256)
void build_cs(const float* __restrict__ freqs)
{
    int i = blockIdx.x * 256 + threadIdx.x;
    float f = freqs[i];
    g_cs[i] = make_float2(cosf(f), sinf(f));
}

// ---------------------------------------------------------------------------
// Fused split: x -> single fp16; 4 weights -> fp16 hi + lo. One launch.
// ---------------------------------------------------------------------------
__global__ __launch_bounds__(256)
void split_all(const float* __restrict__ x,
               const float* __restrict__ w0, const float* __restrict__ w1,
               const float* __restrict__ w2, const float* __restrict__ w3,
               h16* __restrict__ xh,
               h16* __restrict__ whb, h16* __restrict__ wlb)
{
    const int XQ = NTOK * HID / 4;
    const int WQ = HID * HID / 4;
    int i = blockIdx.x * 256 + threadIdx.x;
    if (i < XQ) {
        float4 v = ((const float4*)x)[i];
        ((uint2*)xh)[i] = make_uint2(
            packh2(__float2half_rn(v.x), __float2half_rn(v.y)),
            packh2(__float2half_rn(v.z), __float2half_rn(v.w)));
        return;
    }
    int j = i - XQ;
    int widx = j >> 20;
    int off = j & (WQ - 1);
    const float* src = (widx == 0) ? w0 : (widx == 1) ? w1 : (widx == 2) ? w2 : w3;
    h16* dh = whb + (size_t)widx * HID * HID;
    h16* dl = wlb + (size_t)widx * HID * HID;
    float4 v = ((const float4*)src)[off];
    float vv[4] = {v.x, v.y, v.z, v.w};
    h16 hh[4], ll[4];
    #pragma unroll
    for (int q = 0; q < 4; q++) split1h(vv[q], hh[q], ll[q]);
    ((uint2*)dh)[off] = make_uint2(packh2(hh[0], hh[1]), packh2(hh[2], hh[3]));
    ((uint2*)dl)[off] = make_uint2(packh2(ll[0], ll[1]), packh2(ll[2], ll[3]));
}

// ---------------------------------------------------------------------------
// GEMM core: 128x128 tile, cp.async 2-stage, NPROD in {1,2}.
// NPROD=2 MMAs issued in two passes (all-bh then all-bl) to maximize
// accumulator reuse distance (asm volatile pins issue order).
// ---------------------------------------------------------------------------
#define SPAD 40
#define ARR_B   (128*SPAD*2)          // 10240
#define GEMM_SMEM (2 * 3 * ARR_B)     // 61440

template<int NPROD>
__device__ __forceinline__ void gemm_core(
    const h16* __restrict__ pA,
    const h16* __restrict__ pBh, const h16* __restrict__ pBl,
    uint32_t ub, bool ropePerm, float acc[4][4][4])
{
    constexpr int STB = (NPROD == 2 ? 3 : 2) * ARR_B;
    const int t    = threadIdx.x;
    const int wid  = t >> 5;
    const int lane = t & 31;
    const int wm   = wid & 1;
    const int wn   = wid >> 1;
    const int lrow = lane & 15, lcol = lane >> 4;

    int rowL[2], qdL[2];
    #pragma unroll
    for (int r = 0; r < 2; r++) {
        int u = t + (r << 8);
        rowL[r] = u >> 2;
        qdL[r]  = u & 3;
    }

    #pragma unroll
    for (int i = 0; i < 4; i++)
        #pragma unroll
        for (int j = 0; j < 4; j++)
            #pragma unroll
            for (int q = 0; q < 4; q++)
                acc[i][j][q] = 0.f;

    const int NCH = HID / 32;

    auto issue = [&](int c, int buf) {
        uint32_t sb = ub + buf * STB;
        #pragma unroll
        for (int r = 0; r < 2; r++) {
            int row = rowL[r], qd = qdL[r];
            int brow = row;
            if (ropePerm) {
                int gg = row >> 5, ss = row & 31;
                brow = (ss < 16) ? gg*16 + ss : 64 + gg*16 + (ss - 16);
            }
            uint32_t so = (uint32_t)(row * SPAD + qd * 8) * 2;
            size_t   goA = (size_t)row  * HID + (size_t)c * 32 + qd * 8;
            size_t   goB = (size_t)brow * HID + (size_t)c * 32 + qd * 8;
            cpa16(sb + so,           pA + goA);
            cpa16(sb + ARR_B + so,   pBh + goB);
            if (NPROD == 2) cpa16(sb + 2*ARR_B + so, pBl + goB);
        }
        CP_COMMIT();
    };

    issue(0, 0);

    for (int c = 0; c < NCH; c++) {
        CP_WAIT0();
        __syncthreads();
        if (c + 1 < NCH) issue(c + 1, (c + 1) & 1);

        const uint32_t sb  = ub + (c & 1) * STB;
        const uint32_t uA  = sb;
        const uint32_t uBh = sb + ARR_B;
        const uint32_t uBl = sb + 2*ARR_B;

        #pragma unroll
        for (int kh = 0; kh < 2; kh++) {
            uint32_t ah[4][4], bh[2][4], bl[2][4];
            #pragma unroll
            for (int mt = 0; mt < 4; mt++) {
                uint32_t off = (uint32_t)((wm*64 + mt*16 + lrow) * SPAD + kh*16 + lcol*8) * 2;
                ldm4(ah[mt], uA + off);
            }
            #pragma unroll
            for (int n2 = 0; n2 < 2; n2++) {
                uint32_t off = (uint32_t)((wn*32 + n2*16 + lrow) * SPAD + kh*16 + lcol*8) * 2;
                ldm4(bh[n2], uBh + off);
                if (NPROD == 2) ldm4(bl[n2], uBl + off);
            }
            // pass 1: all hi products (16 independent accumulators)
            #pragma unroll
            for (int mt = 0; mt < 4; mt++)
                #pragma unroll
                for (int nt = 0; nt < 4; nt++) {
                    int n2 = nt >> 1, hb = nt & 1;
                    mma16816(acc[mt][nt], ah[mt], bh[n2][hb], bh[n2][hb+2]);
                }
            // pass 2: all lo products
            if (NPROD == 2) {
                #pragma unroll
                for (int mt = 0; mt < 4; mt++)
                    #pragma unroll
                    for (int nt = 0; nt < 4; nt++) {
                        int n2 = nt >> 1, hb = nt & 1;
                        mma16816(acc[mt][nt], ah[mt], bl[n2][hb], bl[n2][hb+2]);
                    }
            }
        }
    }
}

// ---------------------------------------------------------------------------
// Fused QKV projection launch. grid (48, 32).
// ---------------------------------------------------------------------------
__global__ __launch_bounds__(256)
void mma_gemm_qkv(const h16* __restrict__ xh,
                  const h16* __restrict__ whb, const h16* __restrict__ wlb)
{
    extern __shared__ char dsm[];
    const uint32_t ub = smem_u32(dsm);

    const int t    = threadIdx.x;
    const int wid  = t >> 5;
    const int lane = t & 31;
    const int m0   = blockIdx.y << 7;
    const int wm   = wid & 1;
    const int wn   = wid >> 1;
    const int widx = blockIdx.x >> 4;
    const int n0   = (blockIdx.x & 15) << 7;
    const int h    = n0 >> 7;

    const h16* pA  = xh + (size_t)m0 * HID;
    const h16* pBh = whb + (size_t)widx * HID * HID + (size_t)n0 * HID;
    const h16* pBl = wlb + (size_t)widx * HID * HID + (size_t)n0 * HID;

    float acc[4][4][4];
    const int rbase = wm*64 + (lane >> 2);

    if (widx < 2) {
        gemm_core<1>(pA, pBh, nullptr, ub, true, acc);
        h16* outp = (widx == 0) ? g_Qf : g_Kf;
        const int dd0 = wn*16 + 2*(lane & 3);
        #pragma unroll
        for (int mt = 0; mt < 4; mt++)
            #pragma unroll
            for (int ntp = 0; ntp < 2; ntp++) {
                int d = dd0 + ntp*8;
                #pragma unroll
                for (int rr = 0; rr < 2; rr++) {
                    int r0 = m0 + rbase + mt*16 + rr*8;
                    int b  = r0 >> 11;
                    int s  = r0 & (SEQ - 1);
                    const float2* trow = g_cs + (size_t)s * DHEAD;
                    float2 cs1a = trow[d],      cs1b = trow[d+1];
                    float2 cs2a = trow[d+64],   cs2b = trow[d+65];
                    float x1a = acc[mt][ntp][rr*2+0],   x1b = acc[mt][ntp][rr*2+1];
                    float x2a = acc[mt][ntp+2][rr*2+0], x2b = acc[mt][ntp+2][rr*2+1];
                    float y1a = x1a*cs1a.x - x2a*cs1a.y;
                    float y1b = x1b*cs1b.x - x2b*cs1b.y;
                    float y2a = x2a*cs2a.x + x1a*cs2a.y;
                    float y2b = x2b*cs2b.x + x1b*cs2b.y;
                    size_t base = (((size_t)(b*NHEAD + h))*SEQ + s)*DHEAD;
                    *(uint32_t*)&outp[base + d] =
                        packh2(__float2half_rn(y1a), __float2half_rn(y1b));
                    *(uint32_t*)&outp[base + d + 64] =
                        packh2(__float2half_rn(y2a), __float2half_rn(y2b));
                }
            }
    } else {
        gemm_core<2>(pA, pBh, pBl, ub, false, acc);
        const int cbase = wn*32 + 2*(lane & 3);
        #pragma unroll
        for (int mt = 0; mt < 4; mt++)
            #pragma unroll
            for (int nt = 0; nt < 4; nt++) {
                int r0 = m0 + rbase + mt*16;
                int b  = r0 >> 11;
                int s  = r0 & (SEQ - 1);
                int d  = cbase + nt*8;
                size_t base = (((size_t)(b*NHEAD + h))*SEQ + s)*DHEAD + d;
                uint32_t hp, lp;
                split2packh(acc[mt][nt][0], acc[mt][nt][1], hp, lp);
                *(uint32_t*)&g_Vh[base] = hp;
                *(uint32_t*)&g_Vl[base] = lp;
                split2packh(acc[mt][nt][2], acc[mt][nt][3], hp, lp);
                *(uint32_t*)&g_Vh[base + 8*DHEAD] = hp;
                *(uint32_t*)&g_Vl[base + 8*DHEAD] = lp;
            }
    }
}

// ---------------------------------------------------------------------------
// Final O projection: 2-product (ctx single, Wo hi/lo), fp32 output.
// ---------------------------------------------------------------------------
__global__ __launch_bounds__(256)
void mma_gemm_o(const h16* __restrict__ ch,
                const h16* __restrict__ wh, const h16* __restrict__ wl,
                float* __restrict__ Cout)
{
    extern __shared__ char dsm[];
    const uint32_t ub = smem_u32(dsm);

    const int t    = threadIdx.x;
    const int wid  = t >> 5;
    const int lane = t & 31;
    const int m0   = blockIdx.y << 7;
    const int n0   = blockIdx.x << 7;
    const int wm   = wid & 1;
    const int wn   = wid >> 1;

    float acc[4][4][4];
    gemm_core<2>(ch + (size_t)m0 * HID,
                 wh + (size_t)n0 * HID, wl + (size_t)n0 * HID,
                 ub, false, acc);

    const int rbase = wm*64 + (lane >> 2);
    const int cbase = wn*32 + 2*(lane & 3);
    #pragma unroll
    for (int mt = 0; mt < 4; mt++)
        #pragma unroll
        for (int nt = 0; nt < 4; nt++) {
            int r0 = m0 + rbase + mt*16;
            int cc = n0 + cbase + nt*8;
            *(float2*)&Cout[(size_t)r0 * HID + cc]       = make_float2(acc[mt][nt][0], acc[mt][nt][1]);
            *(float2*)&Cout[(size_t)(r0 + 8) * HID + cc] = make_float2(acc[mt][nt][2], acc[mt][nt][3]);
        }
}

// ---------------------------------------------------------------------------
// Flash attention: BK=32, K/V cp.async 2-stage, 2 CTAs/SM.
// PV MMAs issued in hi-pass/lo-pass pairs for accumulator independence.
// Bias (mask+alibi) fp32 (R11 arithmetic).
// ---------------------------------------------------------------------------
#define BQ 128
#define BK 32
#define QSTR 136
#define KSTR 136
#define QARR (128*QSTR*2)        // 34816
#define KARR (32*KSTR*2)         // 8704 per KV array
#define KVSTAGE (3*KARR)         // 26112
#define OFF_KV QARR
#define FLASH_SMEM (QARR + 2*KVSTAGE)   // 87040

__global__ __launch_bounds__(256, 2)
void flash_mma(const float* __restrict__ mask, const float* __restrict__ alibi)
{
    extern __shared__ char sm[];
    const uint32_t ub = smem_u32(sm);
    const uint32_t uQ = ub;
    h16* sQ = (h16*)sm;

    const int t    = threadIdx.x;
    const int lane = t & 31;
    const int wid  = t >> 5;
    const int qb   = blockIdx.x;
    const int bhid = blockIdx.y;
    const int h    = bhid & (NHEAD - 1);
    const int b    = bhid >> 4;
    const int qi0  = qb * BQ;
    const size_t hbase = (size_t)bhid * SEQ * DHEAD;

    const int lrow = lane & 15, lcol = lane >> 4;
    const int g = lane >> 2, tq = lane & 3;
    const float SCALE = 0.08838834764831845f;  // 1/sqrt(128)

    // Q tile load (sync stores)
    #pragma unroll
    for (int rep = 0; rep < 8; rep++) {
        int u = t + rep * 256;
        int row = u >> 4, c8 = (u & 15) * 8;
        *(uint4*)&sQ[row*QSTR + c8] =
            *(const uint4*)(g_Qf + hbase + (size_t)(qi0 + row) * DHEAD + c8);
    }

    // KV async stage loader: K single, V hi/lo (32 rows each)
    auto issueKV = [&](int kt) {
        uint32_t sb = ub + OFF_KV + (kt & 1) * KVSTAGE;
        const int kj0 = kt * BK;
        #pragma unroll
        for (int rep = 0; rep < 2; rep++) {
            int u = t + rep * 256;
            int row = u >> 4, c8 = (u & 15) * 8;
            uint32_t so = (uint32_t)(row * KSTR + c8) * 2;
            size_t   go = hbase + (size_t)(kj0 + row) * DHEAD + c8;
            cpa16(sb + so,          g_Kf + go);
            cpa16(sb + KARR + so,   g_Vh + go);
            cpa16(sb + 2*KARR + so, g_Vl + go);
        }
        CP_COMMIT();
    };
    issueKV(0);

    float o[16][4];
    #pragma unroll
    for (int nt = 0; nt < 16; nt++)
        #pragma unroll
        for (int q = 0; q < 4; q++)
            o[nt][q] = 0.f;
    float m0r = -1e30f, m8r = -1e30f, l0r = 0.f, l8r = 0.f;
    const int r0g = qi0 + wid*16 + g;

    for (int kt = 0; kt < SEQ / BK; kt++) {
        const int kj0 = kt * BK;
        CP_WAIT0();
        __syncthreads();
        if (kt + 1 < SEQ / BK) issueKV(kt + 1);

        const uint32_t sb  = ub + OFF_KV + (kt & 1) * KVSTAGE;
        const uint32_t uK  = sb;
        const uint32_t uVh = sb + KARR, uVl = sb + 2*KARR;

        // ---- S = Q K^T : warp tile 16 x 32, single product ----
        float sacc[4][4];
        #pragma unroll
        for (int nt = 0; nt < 4; nt++)
            #pragma unroll
            for (int q = 0; q < 4; q++)
                sacc[nt][q] = 0.f;

        #pragma unroll
        for (int kk = 0; kk < 8; kk++) {
            uint32_t qa[4], kb[2][4];
            uint32_t qoff = (uint32_t)((wid*16 + lrow)*QSTR + kk*16 + lcol*8) * 2;
            ldm4(qa, uQ + qoff);
            #pragma unroll
            for (int n2 = 0; n2 < 2; n2++) {
                uint32_t koff = (uint32_t)((n2*16 + lrow)*KSTR + kk*16 + lcol*8) * 2;
                ldm4(kb[n2], uK + koff);
            }
            #pragma unroll
            for (int nt = 0; nt < 4; nt++) {
                int n2 = nt >> 1, hb = nt & 1;
                mma16816(sacc[nt], qa, kb[n2][hb], kb[n2][hb+2]);
            }
        }

        // ---- scale + mask + alibi (fp32), row max (intra-warp only) ----
        float rmax0 = -1e30f, rmax8 = -1e30f;
        #pragma unroll
        for (int nt = 0; nt < 4; nt++) {
            int col = kj0 + nt*8 + 2*tq;
            float2 av  = *(const float2*)(alibi + (size_t)h * SEQ + col);
            float2 mv0 = *(const float2*)(mask + (size_t)r0g * SEQ + col);
            float2 mv1 = *(const float2*)(mask + (size_t)(r0g + 8) * SEQ + col);
            sacc[nt][0] = fmaf(sacc[nt][0], SCALE, mv0.x + av.x);
            sacc[nt][1] = fmaf(sacc[nt][1], SCALE, mv0.y + av.y);
            sacc[nt][2] = fmaf(sacc[nt][2], SCALE, mv1.x + av.x);
            sacc[nt][3] = fmaf(sacc[nt][3], SCALE, mv1.y + av.y);
            rmax0 = fmaxf(rmax0, fmaxf(sacc[nt][0], sacc[nt][1]));
            rmax8 = fmaxf(rmax8, fmaxf(sacc[nt][2], sacc[nt][3]));
        }
        #pragma unroll
        for (int off = 1; off <= 2; off <<= 1) {
            rmax0 = fmaxf(rmax0, __shfl_xor_sync(0xffffffffu, rmax0, off));
            rmax8 = fmaxf(rmax8, __shfl_xor_sync(0xffffffffu, rmax8, off));
        }

        float nm0 = fmaxf(m0r, rmax0), nm8 = fmaxf(m8r, rmax8);
        float c0 = __expf(m0r - nm0),  c8 = __expf(m8r - nm8);
        m0r = nm0; m8r = nm8;

        // ---- exp + pack P fragments (single fp16) ----
        float rs0 = 0.f, rs8 = 0.f;
        uint32_t ph[2][4];
        #pragma unroll
        for (int kk = 0; kk < 2; kk++) {
            #pragma unroll
            for (int half = 0; half < 2; half++) {
                int nt = 2*kk + half;
                float p0 = __expf(sacc[nt][0] - nm0);
                float p1 = __expf(sacc[nt][1] - nm0);
                float p2 = __expf(sacc[nt][2] - nm8);
                float p3 = __expf(sacc[nt][3] - nm8);
                rs0 += p0 + p1; rs8 += p2 + p3;
                ph[kk][half*2+0] = packh2(__float2half_rn(p0), __float2half_rn(p1));
                ph[kk][half*2+1] = packh2(__float2half_rn(p2), __float2half_rn(p3));
            }
        }
        #pragma unroll
        for (int off = 1; off <= 2; off <<= 1) {
            rs0 += __shfl_xor_sync(0xffffffffu, rs0, off);
            rs8 += __shfl_xor_sync(0xffffffffu, rs8, off);
        }
        l0r = l0r * c0 + rs0;
        l8r = l8r * c8 + rs8;

        // ---- rescale O ----
        #pragma unroll
        for (int nt = 0; nt < 16; nt++) {
            o[nt][0] *= c0; o[nt][1] *= c0;
            o[nt][2] *= c8; o[nt][3] *= c8;
        }

        // ---- O += P (Vh + Vl), dd-pairs with hi-pass then lo-pass ----
        #pragma unroll
        for (int kk = 0; kk < 2; kk++) {
            #pragma unroll
            for (int dp = 0; dp < 4; dp++) {
                int dd0 = dp*2, dd1 = dp*2 + 1;
                uint32_t vh0[4], vh1[4], vl0[4], vl1[4];
                uint32_t vo0 = (uint32_t)((kk*16 + lrow)*KSTR + dd0*16 + lcol*8) * 2;
                uint32_t vo1 = (uint32_t)((kk*16 + lrow)*KSTR + dd1*16 + lcol*8) * 2;
                ldm4t(vh0, uVh + vo0);
                ldm4t(vh1, uVh + vo1);
                ldm4t(vl0, uVl + vo0);
                ldm4t(vl1, uVl + vo1);
                // hi pass: 4 independent accumulators
                mma16816(o[dd0*2+0], ph[kk], vh0[0], vh0[1]);
                mma16816(o[dd0*2+1], ph[kk], vh0[2], vh0[3]);
                mma16816(o[dd1*2+0], ph[kk], vh1[0], vh1[1]);
                mma16816(o[dd1*2+1], ph[kk], vh1[2], vh1[3]);
                // lo pass
                mma16816(o[dd0*2+0], ph[kk], vl0[0], vl0[1]);
                mma16816(o[dd0*2+1], ph[kk], vl0[2], vl0[3]);
                mma16816(o[dd1*2+0], ph[kk], vl1[0], vl1[1]);
                mma16816(o[dd1*2+1], ph[kk], vl1[2], vl1[3]);
            }
        }
    }

    // ---- epilogue: normalize, write ctx as single fp16 [tok][h*128+d] ----
    float inv0 = 1.f / l0r, inv8 = 1.f / l8r;
    size_t tok0 = ((size_t)(b*SEQ + qi0 + wid*16 + g)) * HID + h * DHEAD;
    size_t tok8 = tok0 + (size_t)8 * HID;
    #pragma unroll
    for (int nt = 0; nt < 16; nt++) {
        int d = nt*8 + 2*tq;
        *(uint32_t*)&g_ch[tok0 + d] =
            packh2(__float2half_rn(o[nt][0]*inv0), __float2half_rn(o[nt][1]*inv0));
        *(uint32_t*)&g_ch[tok8 + d] =
            packh2(__float2half_rn(o[nt][2]*inv8), __float2half_rn(o[nt][3]*inv8));
    }
}

// ---------------------------------------------------------------------------
extern "C" void kernel_launch(void* const* d_in, const int* in_sizes, int n_in,
                              void* d_out, int out_size)
{
    const float* x     = (const float*)d_in[0];
    const float* mask  = (const float*)d_in[1];
    const float* alibi = (const float*)d_in[2];
    const float* freqs = (const float*)d_in[3];
    const float* W[4]  = { (const float*)d_in[4], (const float*)d_in[5],
                           (const float*)d_in[6], (const float*)d_in[7] };
    float* out = (float*)d_out;
    (void)in_sizes; (void)n_in; (void)out_size;

    cudaFuncSetAttribute(flash_mma,
                         cudaFuncAttributeMaxDynamicSharedMemorySize, FLASH_SMEM);
    cudaFuncSetAttribute(mma_gemm_qkv,
                         cudaFuncAttributeMaxDynamicSharedMemorySize, GEMM_SMEM);
    cudaFuncSetAttribute(mma_gemm_o,
                         cudaFuncAttributeMaxDynamicSharedMemorySize, GEMM_SMEM);

    h16 *xh, *ch, *whbase, *wlbase;
    cudaGetSymbolAddress((void**)&xh, g_xh);
    cudaGetSymbolAddress((void**)&ch, g_ch);
    cudaGetSymbolAddress((void**)&whbase, g_wh);
    cudaGetSymbolAddress((void**)&wlbase, g_wl);

    {
        int total = (NTOK * HID + 4 * HID * HID) / 4;
        split_all<<<(total + 255) / 256, 256>>>(
            x, W[0], W[1], W[2], W[3], xh, whbase, wlbase);
        build_cs<<<(SEQ * DHEAD) / 256, 256>>>(freqs);
    }

    // Fused Q/K (1-product + RoPE) and V (2-product) projections
    mma_gemm_qkv<<<dim3(48, NTOK/128), 256, GEMM_SMEM>>>(xh, whbase, wlbase);

    flash_mma<<<dim3(SEQ/BQ, NBATCH*NHEAD), 256, FLASH_SMEM>>>(mask, alibi);

    // O projection: 2-product (ctx single, Wo hi/lo)
    mma_gemm_o<<<dim3(16, NTOK/128), 256, GEMM_SMEM>>>(
        ch, whbase + 3*(size_t)HID*HID, wlbase + 3*(size_t)HID*HID, out);
}

// round 15
// speedup vs baseline: 1.1211x; 1.0749x over previous
#include <cuda_runtime.h>
#include <cuda_fp16.h>
#include <math.h>
#include <cstdint>

typedef __half h16;

// Problem constants
#define NBATCH 2
#define SEQ    2048
#define NHEAD  16
#define DHEAD  128
#define HID    2048
#define NTOK   4096   // NBATCH*SEQ

// Scratch (device globals — no runtime allocation allowed)
__device__ h16 g_Qf[NBATCH*NHEAD*SEQ*DHEAD];    // post-RoPE, single fp16
__device__ h16 g_Kf[NBATCH*NHEAD*SEQ*DHEAD];
__device__ h16 g_Vf[NBATCH*NHEAD*SEQ*DHEAD];    // V single fp16

__device__ h16 g_xh[(size_t)NTOK*HID];          // x single fp16
__device__ h16 g_ch[(size_t)NTOK*HID];          // ctx single fp16 (flash output)
__device__ h16 g_wh[4][(size_t)HID*HID];        // weights hi/lo
__device__ h16 g_wl[4][(size_t)HID*HID];

__device__ float2 g_cs[SEQ*DHEAD];              // (cos, sin) of freqs

// ---------------------------------------------------------------------------
// helpers
// ---------------------------------------------------------------------------
__device__ __forceinline__ uint32_t smem_u32(const void* p) {
    uint32_t a;
    asm("{ .reg .u64 t; cvta.to.shared.u64 t, %1; cvt.u32.u64 %0, t; }"
        : "=r"(a) : "l"(p));
    return a;
}
__device__ __forceinline__ void ldm4(uint32_t* r, uint32_t addr) {
    asm volatile("ldmatrix.sync.aligned.m8n8.x4.shared.b16 {%0,%1,%2,%3},[%4];"
                 : "=r"(r[0]), "=r"(r[1]), "=r"(r[2]), "=r"(r[3]) : "r"(addr));
}
__device__ __forceinline__ void ldm4t(uint32_t* r, uint32_t addr) {
    asm volatile("ldmatrix.sync.aligned.m8n8.x4.trans.shared.b16 {%0,%1,%2,%3},[%4];"
                 : "=r"(r[0]), "=r"(r[1]), "=r"(r[2]), "=r"(r[3]) : "r"(addr));
}
__device__ __forceinline__ void mma16816(float* d, const uint32_t* a,
                                         uint32_t b0, uint32_t b1) {
    asm volatile(
        "mma.sync.aligned.m16n8k16.row.col.f32.f16.f16.f32 "
        "{%0,%1,%2,%3},{%4,%5,%6,%7},{%8,%9},{%0,%1,%2,%3};"
        : "+f"(d[0]), "+f"(d[1]), "+f"(d[2]), "+f"(d[3])
        : "r"(a[0]), "r"(a[1]), "r"(a[2]), "r"(a[3]), "r"(b0), "r"(b1));
}
__device__ __forceinline__ uint32_t packh2(h16 a, h16 b) {
    return ((uint32_t)__half_as_ushort(b) << 16) | __half_as_ushort(a);
}
__device__ __forceinline__ void split1h(float v, h16& h, h16& l) {
    h = __float2half_rn(v);
    l = __float2half_rn(v - __half2float(h));
}
__device__ __forceinline__ void cpa16(uint32_t s, const void* g) {
    asm volatile("cp.async.cg.shared.global [%0], [%1], 16;" :: "r"(s), "l"(g));
}
#define CP_COMMIT() asm volatile("cp.async.commit_group;" ::: "memory")
#define CP_WAIT0()  asm volatile("cp.async.wait_group 0;" ::: "memory")

// ---------------------------------------------------------------------------
// cos/sin table from freqs
// ---------------------------------------------------------------------------
__global__ __launch_bounds__(256)
void build_cs(const float* __restrict__ freqs)
{
    int i = blockIdx.x * 256 + threadIdx.x;
    float f = freqs[i];
    g_cs[i] = make_float2(cosf(f), sinf(f));
}

// ---------------------------------------------------------------------------
// Fused split: x -> single fp16; 4 weights -> fp16 hi + lo. One launch.
// ---------------------------------------------------------------------------
__global__ __launch_bounds__(256)
void split_all(const float* __restrict__ x,
               const float* __restrict__ w0, const float* __restrict__ w1,
               const float* __restrict__ w2, const float* __restrict__ w3,
               h16* __restrict__ xh,
               h16* __restrict__ whb, h16* __restrict__ wlb)
{
    const int XQ = NTOK * HID / 4;
    const int WQ = HID * HID / 4;
    int i = blockIdx.x * 256 + threadIdx.x;
    if (i < XQ) {
        float4 v = ((const float4*)x)[i];
        ((uint2*)xh)[i] = make_uint2(
            packh2(__float2half_rn(v.x), __float2half_rn(v.y)),
            packh2(__float2half_rn(v.z), __float2half_rn(v.w)));
        return;
    }
    int j = i - XQ;
    int widx = j >> 20;
    int off = j & (WQ - 1);
    const float* src = (widx == 0) ? w0 : (widx == 1) ? w1 : (widx == 2) ? w2 : w3;
    h16* dh = whb + (size_t)widx * HID * HID;
    h16* dl = wlb + (size_t)widx * HID * HID;
    float4 v = ((const float4*)src)[off];
    float vv[4] = {v.x, v.y, v.z, v.w};
    h16 hh[4], ll[4];
    #pragma unroll
    for (int q = 0; q < 4; q++) split1h(vv[q], hh[q], ll[q]);
    ((uint2*)dh)[off] = make_uint2(packh2(hh[0], hh[1]), packh2(hh[2], hh[3]));
    ((uint2*)dl)[off] = make_uint2(packh2(ll[0], ll[1]), packh2(ll[2], ll[3]));
}

// ---------------------------------------------------------------------------
// GEMM core: 128x128 tile, cp.async 2-stage, NPROD in {1,2}.
// NPROD=2 MMAs issued in two passes (all-bh then all-bl).
// ---------------------------------------------------------------------------
#define SPAD 40
#define ARR_B   (128*SPAD*2)          // 10240
#define GEMM_SMEM (2 * 3 * ARR_B)     // 61440

template<int NPROD>
__device__ __forceinline__ void gemm_core(
    const h16* __restrict__ pA,
    const h16* __restrict__ pBh, const h16* __restrict__ pBl,
    uint32_t ub, bool ropePerm, float acc[4][4][4])
{
    constexpr int STB = (NPROD == 2 ? 3 : 2) * ARR_B;
    const int t    = threadIdx.x;
    const int wid  = t >> 5;
    const int lane = t & 31;
    const int wm   = wid & 1;
    const int wn   = wid >> 1;
    const int lrow = lane & 15, lcol = lane >> 4;

    int rowL[2], qdL[2];
    #pragma unroll
    for (int r = 0; r < 2; r++) {
        int u = t + (r << 8);
        rowL[r] = u >> 2;
        qdL[r]  = u & 3;
    }

    #pragma unroll
    for (int i = 0; i < 4; i++)
        #pragma unroll
        for (int j = 0; j < 4; j++)
            #pragma unroll
            for (int q = 0; q < 4; q++)
                acc[i][j][q] = 0.f;

    const int NCH = HID / 32;

    auto issue = [&](int c, int buf) {
        uint32_t sb = ub + buf * STB;
        #pragma unroll
        for (int r = 0; r < 2; r++) {
            int row = rowL[r], qd = qdL[r];
            int brow = row;
            if (ropePerm) {
                int gg = row >> 5, ss = row & 31;
                brow = (ss < 16) ? gg*16 + ss : 64 + gg*16 + (ss - 16);
            }
            uint32_t so = (uint32_t)(row * SPAD + qd * 8) * 2;
            size_t   goA = (size_t)row  * HID + (size_t)c * 32 + qd * 8;
            size_t   goB = (size_t)brow * HID + (size_t)c * 32 + qd * 8;
            cpa16(sb + so,           pA + goA);
            cpa16(sb + ARR_B + so,   pBh + goB);
            if (NPROD == 2) cpa16(sb + 2*ARR_B + so, pBl + goB);
        }
        CP_COMMIT();
    };

    issue(0, 0);

    for (int c = 0; c < NCH; c++) {
        CP_WAIT0();
        __syncthreads();
        if (c + 1 < NCH) issue(c + 1, (c + 1) & 1);

        const uint32_t sb  = ub + (c & 1) * STB;
        const uint32_t uA  = sb;
        const uint32_t uBh = sb + ARR_B;
        const uint32_t uBl = sb + 2*ARR_B;

        #pragma unroll
        for (int kh = 0; kh < 2; kh++) {
            uint32_t ah[4][4], bh[2][4], bl[2][4];
            #pragma unroll
            for (int mt = 0; mt < 4; mt++) {
                uint32_t off = (uint32_t)((wm*64 + mt*16 + lrow) * SPAD + kh*16 + lcol*8) * 2;
                ldm4(ah[mt], uA + off);
            }
            #pragma unroll
            for (int n2 = 0; n2 < 2; n2++) {
                uint32_t off = (uint32_t)((wn*32 + n2*16 + lrow) * SPAD + kh*16 + lcol*8) * 2;
                ldm4(bh[n2], uBh + off);
                if (NPROD == 2) ldm4(bl[n2], uBl + off);
            }
            #pragma unroll
            for (int mt = 0; mt < 4; mt++)
                #pragma unroll
                for (int nt = 0; nt < 4; nt++) {
                    int n2 = nt >> 1, hb = nt & 1;
                    mma16816(acc[mt][nt], ah[mt], bh[n2][hb], bh[n2][hb+2]);
                }
            if (NPROD == 2) {
                #pragma unroll
                for (int mt = 0; mt < 4; mt++)
                    #pragma unroll
                    for (int nt = 0; nt < 4; nt++) {
                        int n2 = nt >> 1, hb = nt & 1;
                        mma16816(acc[mt][nt], ah[mt], bl[n2][hb], bl[n2][hb+2]);
                    }
            }
        }
    }
}

// ---------------------------------------------------------------------------
// Fused QKV projection launch. grid (48, 32).
//   widx 0/1 -> Q/K: 1-product + RoPE epilogue (single fp16 out).
//   widx 2   -> V: 2-product, single fp16 out.
// ---------------------------------------------------------------------------
__global__ __launch_bounds__(256)
void mma_gemm_qkv(const h16* __restrict__ xh,
                  const h16* __restrict__ whb, const h16* __restrict__ wlb)
{
    extern __shared__ char dsm[];
    const uint32_t ub = smem_u32(dsm);

    const int t    = threadIdx.x;
    const int wid  = t >> 5;
    const int lane = t & 31;
    const int m0   = blockIdx.y << 7;
    const int wm   = wid & 1;
    const int wn   = wid >> 1;
    const int widx = blockIdx.x >> 4;
    const int n0   = (blockIdx.x & 15) << 7;
    const int h    = n0 >> 7;

    const h16* pA  = xh + (size_t)m0 * HID;
    const h16* pBh = whb + (size_t)widx * HID * HID + (size_t)n0 * HID;
    const h16* pBl = wlb + (size_t)widx * HID * HID + (size_t)n0 * HID;

    float acc[4][4][4];
    const int rbase = wm*64 + (lane >> 2);

    if (widx < 2) {
        gemm_core<1>(pA, pBh, nullptr, ub, true, acc);
        h16* outp = (widx == 0) ? g_Qf : g_Kf;
        const int dd0 = wn*16 + 2*(lane & 3);
        #pragma unroll
        for (int mt = 0; mt < 4; mt++)
            #pragma unroll
            for (int ntp = 0; ntp < 2; ntp++) {
                int d = dd0 + ntp*8;
                #pragma unroll
                for (int rr = 0; rr < 2; rr++) {
                    int r0 = m0 + rbase + mt*16 + rr*8;
                    int b  = r0 >> 11;
                    int s  = r0 & (SEQ - 1);
                    const float2* trow = g_cs + (size_t)s * DHEAD;
                    float2 cs1a = trow[d],      cs1b = trow[d+1];
                    float2 cs2a = trow[d+64],   cs2b = trow[d+65];
                    float x1a = acc[mt][ntp][rr*2+0],   x1b = acc[mt][ntp][rr*2+1];
                    float x2a = acc[mt][ntp+2][rr*2+0], x2b = acc[mt][ntp+2][rr*2+1];
                    float y1a = x1a*cs1a.x - x2a*cs1a.y;
                    float y1b = x1b*cs1b.x - x2b*cs1b.y;
                    float y2a = x2a*cs2a.x + x1a*cs2a.y;
                    float y2b = x2b*cs2b.x + x1b*cs2b.y;
                    size_t base = (((size_t)(b*NHEAD + h))*SEQ + s)*DHEAD;
                    *(uint32_t*)&outp[base + d] =
                        packh2(__float2half_rn(y1a), __float2half_rn(y1b));
                    *(uint32_t*)&outp[base + d + 64] =
                        packh2(__float2half_rn(y2a), __float2half_rn(y2b));
                }
            }
    } else {
        gemm_core<2>(pA, pBh, pBl, ub, false, acc);
        const int cbase = wn*32 + 2*(lane & 3);
        #pragma unroll
        for (int mt = 0; mt < 4; mt++)
            #pragma unroll
            for (int nt = 0; nt < 4; nt++) {
                int r0 = m0 + rbase + mt*16;
                int b  = r0 >> 11;
                int s  = r0 & (SEQ - 1);
                int d  = cbase + nt*8;
                size_t base = (((size_t)(b*NHEAD + h))*SEQ + s)*DHEAD + d;
                *(uint32_t*)&g_Vf[base] =
                    packh2(__float2half_rn(acc[mt][nt][0]), __float2half_rn(acc[mt][nt][1]));
                *(uint32_t*)&g_Vf[base + 8*DHEAD] =
                    packh2(__float2half_rn(acc[mt][nt][2]), __float2half_rn(acc[mt][nt][3]));
            }
    }
}

// ---------------------------------------------------------------------------
// Final O projection: 2-product (ctx single, Wo hi/lo), fp32 output.
// ---------------------------------------------------------------------------
__global__ __launch_bounds__(256)
void mma_gemm_o(const h16* __restrict__ ch,
                const h16* __restrict__ wh, const h16* __restrict__ wl,
                float* __restrict__ Cout)
{
    extern __shared__ char dsm[];
    const uint32_t ub = smem_u32(dsm);

    const int t    = threadIdx.x;
    const int wid  = t >> 5;
    const int lane = t & 31;
    const int m0   = blockIdx.y << 7;
    const int n0   = blockIdx.x << 7;
    const int wm   = wid & 1;
    const int wn   = wid >> 1;

    float acc[4][4][4];
    gemm_core<2>(ch + (size_t)m0 * HID,
                 wh + (size_t)n0 * HID, wl + (size_t)n0 * HID,
                 ub, false, acc);

    const int rbase = wm*64 + (lane >> 2);
    const int cbase = wn*32 + 2*(lane & 3);
    #pragma unroll
    for (int mt = 0; mt < 4; mt++)
        #pragma unroll
        for (int nt = 0; nt < 4; nt++) {
            int r0 = m0 + rbase + mt*16;
            int cc = n0 + cbase + nt*8;
            *(float2*)&Cout[(size_t)r0 * HID + cc]       = make_float2(acc[mt][nt][0], acc[mt][nt][1]);
            *(float2*)&Cout[(size_t)(r0 + 8) * HID + cc] = make_float2(acc[mt][nt][2], acc[mt][nt][3]);
        }
}

// ---------------------------------------------------------------------------
// Flash attention: BK=32, K/V (both single fp16) cp.async 2-stage, 2 CTAs/SM.
// PV single-product.
// ---------------------------------------------------------------------------
#define BQ 128
#define BK 32
#define QSTR 136
#define KSTR 136
#define QARR (128*QSTR*2)        // 34816
#define KARR (32*KSTR*2)         // 8704 per KV array
#define KVSTAGE (2*KARR)         // K + V = 17408
#define OFF_KV QARR
#define FLASH_SMEM (QARR + 2*KVSTAGE)   // 69632

__global__ __launch_bounds__(256, 2)
void flash_mma(const float* __restrict__ mask, const float* __restrict__ alibi)
{
    extern __shared__ char sm[];
    const uint32_t ub = smem_u32(sm);
    const uint32_t uQ = ub;
    h16* sQ = (h16*)sm;

    const int t    = threadIdx.x;
    const int lane = t & 31;
    const int wid  = t >> 5;
    const int qb   = blockIdx.x;
    const int bhid = blockIdx.y;
    const int h    = bhid & (NHEAD - 1);
    const int b    = bhid >> 4;
    const int qi0  = qb * BQ;
    const size_t hbase = (size_t)bhid * SEQ * DHEAD;

    const int lrow = lane & 15, lcol = lane >> 4;
    const int g = lane >> 2, tq = lane & 3;
    const float SCALE = 0.08838834764831845f;  // 1/sqrt(128)

    // Q tile load (sync stores)
    #pragma unroll
    for (int rep = 0; rep < 8; rep++) {
        int u = t + rep * 256;
        int row = u >> 4, c8 = (u & 15) * 8;
        *(uint4*)&sQ[row*QSTR + c8] =
            *(const uint4*)(g_Qf + hbase + (size_t)(qi0 + row) * DHEAD + c8);
    }

    // KV async stage loader: K and V single fp16 (32 rows each)
    auto issueKV = [&](int kt) {
        uint32_t sb = ub + OFF_KV + (kt & 1) * KVSTAGE;
        const int kj0 = kt * BK;
        #pragma unroll
        for (int rep = 0; rep < 2; rep++) {
            int u = t + rep * 256;
            int row = u >> 4, c8 = (u & 15) * 8;
            uint32_t so = (uint32_t)(row * KSTR + c8) * 2;
            size_t   go = hbase + (size_t)(kj0 + row) * DHEAD + c8;
            cpa16(sb + so,        g_Kf + go);
            cpa16(sb + KARR + so, g_Vf + go);
        }
        CP_COMMIT();
    };
    issueKV(0);

    float o[16][4];
    #pragma unroll
    for (int nt = 0; nt < 16; nt++)
        #pragma unroll
        for (int q = 0; q < 4; q++)
            o[nt][q] = 0.f;
    float m0r = -1e30f, m8r = -1e30f, l0r = 0.f, l8r = 0.f;
    const int r0g = qi0 + wid*16 + g;

    for (int kt = 0; kt < SEQ / BK; kt++) {
        const int kj0 = kt * BK;
        CP_WAIT0();
        __syncthreads();
        if (kt + 1 < SEQ / BK) issueKV(kt + 1);

        const uint32_t sb = ub + OFF_KV + (kt & 1) * KVSTAGE;
        const uint32_t uK = sb;
        const uint32_t uV = sb + KARR;

        // ---- S = Q K^T : warp tile 16 x 32, single product ----
        float sacc[4][4];
        #pragma unroll
        for (int nt = 0; nt < 4; nt++)
            #pragma unroll
            for (int q = 0; q < 4; q++)
                sacc[nt][q] = 0.f;

        #pragma unroll
        for (int kk = 0; kk < 8; kk++) {
            uint32_t qa[4], kb[2][4];
            uint32_t qoff = (uint32_t)((wid*16 + lrow)*QSTR + kk*16 + lcol*8) * 2;
            ldm4(qa, uQ + qoff);
            #pragma unroll
            for (int n2 = 0; n2 < 2; n2++) {
                uint32_t koff = (uint32_t)((n2*16 + lrow)*KSTR + kk*16 + lcol*8) * 2;
                ldm4(kb[n2], uK + koff);
            }
            #pragma unroll
            for (int nt = 0; nt < 4; nt++) {
                int n2 = nt >> 1, hb = nt & 1;
                mma16816(sacc[nt], qa, kb[n2][hb], kb[n2][hb+2]);
            }
        }

        // ---- scale + mask + alibi (fp32), row max (intra-warp only) ----
        float rmax0 = -1e30f, rmax8 = -1e30f;
        #pragma unroll
        for (int nt = 0; nt < 4; nt++) {
            int col = kj0 + nt*8 + 2*tq;
            float2 av  = *(const float2*)(alibi + (size_t)h * SEQ + col);
            float2 mv0 = *(const float2*)(mask + (size_t)r0g * SEQ + col);
            float2 mv1 = *(const float2*)(mask + (size_t)(r0g + 8) * SEQ + col);
            sacc[nt][0] = fmaf(sacc[nt][0], SCALE, mv0.x + av.x);
            sacc[nt][1] = fmaf(sacc[nt][1], SCALE, mv0.y + av.y);
            sacc[nt][2] = fmaf(sacc[nt][2], SCALE, mv1.x + av.x);
            sacc[nt][3] = fmaf(sacc[nt][3], SCALE, mv1.y + av.y);
            rmax0 = fmaxf(rmax0, fmaxf(sacc[nt][0], sacc[nt][1]));
            rmax8 = fmaxf(rmax8, fmaxf(sacc[nt][2], sacc[nt][3]));
        }
        #pragma unroll
        for (int off = 1; off <= 2; off <<= 1) {
            rmax0 = fmaxf(rmax0, __shfl_xor_sync(0xffffffffu, rmax0, off));
            rmax8 = fmaxf(rmax8, __shfl_xor_sync(0xffffffffu, rmax8, off));
        }

        float nm0 = fmaxf(m0r, rmax0), nm8 = fmaxf(m8r, rmax8);
        float c0 = __expf(m0r - nm0),  c8 = __expf(m8r - nm8);
        m0r = nm0; m8r = nm8;

        // ---- exp + pack P fragments (single fp16) ----
        float rs0 = 0.f, rs8 = 0.f;
        uint32_t ph[2][4];
        #pragma unroll
        for (int kk = 0; kk < 2; kk++) {
            #pragma unroll
            for (int half = 0; half < 2; half++) {
                int nt = 2*kk + half;
                float p0 = __expf(sacc[nt][0] - nm0);
                float p1 = __expf(sacc[nt][1] - nm0);
                float p2 = __expf(sacc[nt][2] - nm8);
                float p3 = __expf(sacc[nt][3] - nm8);
                rs0 += p0 + p1; rs8 += p2 + p3;
                ph[kk][half*2+0] = packh2(__float2half_rn(p0), __float2half_rn(p1));
                ph[kk][half*2+1] = packh2(__float2half_rn(p2), __float2half_rn(p3));
            }
        }
        #pragma unroll
        for (int off = 1; off <= 2; off <<= 1) {
            rs0 += __shfl_xor_sync(0xffffffffu, rs0, off);
            rs8 += __shfl_xor_sync(0xffffffffu, rs8, off);
        }
        l0r = l0r * c0 + rs0;
        l8r = l8r * c8 + rs8;

        // ---- rescale O ----
        #pragma unroll
        for (int nt = 0; nt < 16; nt++) {
            o[nt][0] *= c0; o[nt][1] *= c0;
            o[nt][2] *= c8; o[nt][3] *= c8;
        }

        // ---- O += P V : single product ----
        #pragma unroll
        for (int kk = 0; kk < 2; kk++) {
            #pragma unroll
            for (int dp = 0; dp < 4; dp++) {
                int dd0 = dp*2, dd1 = dp*2 + 1;
                uint32_t v0[4], v1[4];
                uint32_t vo0 = (uint32_t)((kk*16 + lrow)*KSTR + dd0*16 + lcol*8) * 2;
                uint32_t vo1 = (uint32_t)((kk*16 + lrow)*KSTR + dd1*16 + lcol*8) * 2;
                ldm4t(v0, uV + vo0);
                ldm4t(v1, uV + vo1);
                mma16816(o[dd0*2+0], ph[kk], v0[0], v0[1]);
                mma16816(o[dd0*2+1], ph[kk], v0[2], v0[3]);
                mma16816(o[dd1*2+0], ph[kk], v1[0], v1[1]);
                mma16816(o[dd1*2+1], ph[kk], v1[2], v1[3]);
            }
        }
    }

    // ---- epilogue: normalize, write ctx as single fp16 [tok][h*128+d] ----
    float inv0 = 1.f / l0r, inv8 = 1.f / l8r;
    size_t tok0 = ((size_t)(b*SEQ + qi0 + wid*16 + g)) * HID + h * DHEAD;
    size_t tok8 = tok0 + (size_t)8 * HID;
    #pragma unroll
    for (int nt = 0; nt < 16; nt++) {
        int d = nt*8 + 2*tq;
        *(uint32_t*)&g_ch[tok0 + d] =
            packh2(__float2half_rn(o[nt][0]*inv0), __float2half_rn(o[nt][1]*inv0));
        *(uint32_t*)&g_ch[tok8 + d] =
            packh2(__float2half_rn(o[nt][2]*inv8), __float2half_rn(o[nt][3]*inv8));
    }
}

// ---------------------------------------------------------------------------
extern "C" void kernel_launch(void* const* d_in, const int* in_sizes, int n_in,
                              void* d_out, int out_size)
{
    const float* x     = (const float*)d_in[0];
    const float* mask  = (const float*)d_in[1];
    const float* alibi = (const float*)d_in[2];
    const float* freqs = (const float*)d_in[3];
    const float* W[4]  = { (const float*)d_in[4], (const float*)d_in[5],
                           (const float*)d_in[6], (const float*)d_in[7] };
    float* out = (float*)d_out;
    (void)in_sizes; (void)n_in; (void)out_size;

    cudaFuncSetAttribute(flash_mma,
                         cudaFuncAttributeMaxDynamicSharedMemorySize, FLASH_SMEM);
    cudaFuncSetAttribute(mma_gemm_qkv,
                         cudaFuncAttributeMaxDynamicSharedMemorySize, GEMM_SMEM);
    cudaFuncSetAttribute(mma_gemm_o,
                         cudaFuncAttributeMaxDynamicSharedMemorySize, GEMM_SMEM);

    h16 *xh, *ch, *whbase, *wlbase;
    cudaGetSymbolAddress((void**)&xh, g_xh);
    cudaGetSymbolAddress((void**)&ch, g_ch);
    cudaGetSymbolAddress((void**)&whbase, g_wh);
    cudaGetSymbolAddress((void**)&wlbase, g_wl);

    {
        int total = (NTOK * HID + 4 * HID * HID) / 4;
        split_all<<<(total + 255) / 256, 256>>>(
            x, W[0], W[1], W[2], W[3], xh, whbase, wlbase);
        build_cs<<<(SEQ * DHEAD) / 256, 256>>>(freqs);
    }

    // Fused Q/K (1-product + RoPE) and V (2-product) projections
    mma_gemm_qkv<<<dim3(48, NTOK/128), 256, GEMM_SMEM>>>(xh, whbase, wlbase);

    flash_mma<<<dim3(SEQ/BQ, NBATCH*NHEAD), 256, FLASH_SMEM>>>(mask, alibi);

    // O projection: 2-product (ctx single, Wo hi/lo)
    mma_gemm_o<<<dim3(16, NTOK/128), 256, GEMM_SMEM>>>(
        ch, whbase + 3*(size_t)HID*HID, wlbase + 3*(size_t)HID*HID, out);
}